// round 14
// baseline (speedup 1.0000x reference)
#include <cuda_runtime.h>
#include <cuda_bf16.h>
#include <math.h>
#include <stdint.h>

// Shapes (fixed by the problem)
#define TDIM 2048   // T == S
#define CDIM 512    // I == O == E == Ev
#define BB   2
#define NBH  16     // B*H
#define DK   64     // KEY_DIM == VALUE_DIM
#define HKT  (DK * TDIM / 2)      // uint32 (bf16x2) per bh plane

// Pre-split bf16 hi/lo packed (bf16x2 along the fast axis) device scratch.
__device__ uint32_t g_Kh[NBH * HKT], g_Kl[NBH * HKT];
__device__ uint32_t g_Vh[NBH * HKT], g_Vl[NBH * HKT];
__device__ uint32_t g_Qh[NBH * HKT], g_Ql[NBH * HKT];
__device__ uint32_t g_Oh[BB * CDIM * TDIM / 2], g_Ol[BB * CDIM * TDIM / 2];
__device__ uint32_t g_Xh[BB * CDIM * TDIM / 2], g_Xl[BB * CDIM * TDIM / 2];
__device__ uint32_t g_Yh[BB * CDIM * TDIM / 2], g_Yl[BB * CDIM * TDIM / 2];
__device__ uint32_t g_Wph[4 * CDIM * CDIM / 2], g_Wpl[4 * CDIM * CDIM / 2];

// ============================================================================
// Warp-MMA helpers (baseline PTX: works on plain sm_103 target)
// ============================================================================
__device__ __forceinline__ uint32_t smem_u32(const void* p) {
    uint32_t a;
    asm("{ .reg .u64 t; cvta.to.shared.u64 t, %1; cvt.u32.u64 %0, t; }"
        : "=r"(a) : "l"(p));
    return a;
}
__device__ __forceinline__ void ldsm_x4(uint32_t addr, uint32_t* r) {
    asm volatile("ldmatrix.sync.aligned.m8n8.x4.shared.b16 {%0,%1,%2,%3}, [%4];"
                 : "=r"(r[0]), "=r"(r[1]), "=r"(r[2]), "=r"(r[3]) : "r"(addr));
}
__device__ __forceinline__ void ldsm_x4t(uint32_t addr, uint32_t* r) {
    asm volatile("ldmatrix.sync.aligned.m8n8.x4.trans.shared.b16 {%0,%1,%2,%3}, [%4];"
                 : "=r"(r[0]), "=r"(r[1]), "=r"(r[2]), "=r"(r[3]) : "r"(addr));
}
__device__ __forceinline__ uint32_t movm(uint32_t s) {
    uint32_t d;
    asm volatile("movmatrix.sync.aligned.m8n8.trans.b16 %0, %1;"
                 : "=r"(d) : "r"(s));
    return d;
}
__device__ __forceinline__ void mma_bf16(float* d, const uint32_t* a,
                                         const uint32_t* b) {
    asm volatile(
        "mma.sync.aligned.m16n8k16.row.col.f32.bf16.bf16.f32 "
        "{%0,%1,%2,%3}, {%4,%5,%6,%7}, {%8,%9}, {%0,%1,%2,%3};"
        : "+f"(d[0]), "+f"(d[1]), "+f"(d[2]), "+f"(d[3])
        : "r"(a[0]), "r"(a[1]), "r"(a[2]), "r"(a[3]), "r"(b[0]), "r"(b[1]));
}
__device__ __forceinline__ void cpa16(uint32_t smem_dst, const void* gsrc) {
    asm volatile("cp.async.cg.shared.global [%0], [%1], 16;"
                 :: "r"(smem_dst), "l"(gsrc));
}
#define CPA_COMMIT() asm volatile("cp.async.commit_group;" ::: "memory")
#define CPA_WAIT0()  asm volatile("cp.async.wait_group 0;" ::: "memory")
#define CPA_WAIT1()  asm volatile("cp.async.wait_group 1;" ::: "memory")

__device__ __forceinline__ uint32_t pack2(float lo, float hi) {
    uint32_t r;
    asm("cvt.rn.bf16x2.f32 %0, %1, %2;" : "=r"(r) : "f"(hi), "f"(lo));
    return r;
}
__device__ __forceinline__ void split2(float a, float b, uint32_t& hi, uint32_t& lo) {
    hi = pack2(a, b);
    float ha = __int_as_float(hi << 16);
    float hb = __int_as_float(hi & 0xffff0000u);
    lo = pack2(a - ha, b - hb);
}
__device__ __forceinline__ void split4(float4 v, uint2& hi, uint2& lo) {
    split2(v.x, v.y, hi.x, lo.x);
    split2(v.z, v.w, hi.y, lo.y);
}

// MUFU-pipe exp2 (tensor cores own GEMMs; MUFU is otherwise idle)
__device__ __forceinline__ float ex2a(float x) {
    float y;
    asm("ex2.approx.f32 %0, %1;" : "=f"(y) : "f"(x));
    return y;
}
#define C_EXP8 0.18033688f   // log2(e) / 8

// ============================================================================
// Prep: split x, y, and all weights into packed bf16 hi/lo
// ============================================================================
#define PREP_THREADS (524288 * 2 + 4 * 65536)   // 1,310,720

__global__ void __launch_bounds__(256) prep_split(
    const float* __restrict__ x, const float* __restrict__ y,
    const float* __restrict__ Wk, const float* __restrict__ Wv,
    const float* __restrict__ Wq, const float* __restrict__ Wf)
{
    int idx = blockIdx.x * 256 + threadIdx.x;
    const float* src; uint32_t* dh; uint32_t* dl; size_t off, dst;
    if (idx < 524288) {
        src = x; dh = g_Xh; dl = g_Xl; off = idx; dst = (size_t)idx * 2;
    } else if (idx < 1048576) {
        int w = idx - 524288;
        src = y; dh = g_Yh; dl = g_Yl; off = w; dst = (size_t)w * 2;
    } else {
        int w = idx - 1048576;
        int pj = w >> 16, loc = w & 65535;
        src = (pj == 0) ? Wk : (pj == 1) ? Wv : (pj == 2) ? Wq : Wf;
        dh = g_Wph; dl = g_Wpl; off = loc; dst = (size_t)w * 2;
    }
    float4 v = *(const float4*)(src + off * 4);
    uint2 hi, lo; split4(v, hi, lo);
    dh[dst] = hi.x; dh[dst + 1] = hi.y;
    dl[dst] = lo.x; dl[dst + 1] = lo.y;
}

// ============================================================================
// bf16x3 HMMA GEMM (R12 measured-best: 256 threads, 8 warps 64m x 32n)
// ============================================================================
#define A_STR_B 144
#define B_STR_B 272
#define SA_HI 0
#define SA_LO 18432
#define SB_HI 36864
#define SB_LO 54272
#define STAGE 71680
#define GEMM_SMEM (2 * STAGE)

__device__ __forceinline__ void gemm_fill(uint32_t sbs, const uint32_t* Ah,
                                          const uint32_t* Al, const uint32_t* Bh,
                                          const uint32_t* Bl, int k0, int tid) {
    #pragma unroll
    for (int q = 0; q < 4; q++) {
        int idx = q * 256 + tid, r = idx >> 3, c = idx & 7;
        uint32_t so = (uint32_t)(r * A_STR_B + c * 16);
        size_t gi = (size_t)r * (CDIM / 2) + k0 / 2 + c * 4;
        cpa16(sbs + SA_HI + so, Ah + gi);
        cpa16(sbs + SA_LO + so, Al + gi);
    }
    #pragma unroll
    for (int q = 0; q < 4; q++) {
        int idx = q * 256 + tid, r = idx >> 4, c = idx & 15;
        uint32_t so = (uint32_t)(r * B_STR_B + c * 16);
        size_t gi = (size_t)(k0 + r) * (TDIM / 2) + c * 4;
        cpa16(sbs + SB_HI + so, Bh + gi);
        cpa16(sbs + SB_LO + so, Bl + gi);
    }
}

__global__ void __launch_bounds__(256, 1) gemm_mma(
    const float* __restrict__ bias, float* __restrict__ out, int zbase)
{
    extern __shared__ char smem[];
    uint32_t sb = smem_u32(smem);
    int tid = threadIdx.x, wid = tid >> 5, lane = tid & 31;

    int z = blockIdx.z + zbase;
    int m0 = blockIdx.y * 128, n0 = blockIdx.x * 128;
    const uint32_t *Ah, *Al, *Bh, *Bl;
    uint32_t *Ch = nullptr, *Cl = nullptr;
    float* Od = nullptr;
    size_t cbase = 0;
    if (z < 6) {
        int proj = z >> 1, b = z & 1;
        Ah = g_Wph + (size_t)proj * CDIM * (CDIM / 2);
        Al = g_Wpl + (size_t)proj * CDIM * (CDIM / 2);
        const uint32_t* Xh = (proj == 2) ? g_Yh : g_Xh;
        const uint32_t* Xl = (proj == 2) ? g_Yl : g_Xl;
        Bh = Xh + (size_t)b * CDIM * (TDIM / 2);
        Bl = Xl + (size_t)b * CDIM * (TDIM / 2);
        Ch = (proj == 0) ? g_Kh : (proj == 1) ? g_Vh : g_Qh;
        Cl = (proj == 0) ? g_Kl : (proj == 1) ? g_Vl : g_Ql;
        cbase = (size_t)b * CDIM * (TDIM / 2);
    } else {
        int b = z - 6;
        Ah = g_Wph + (size_t)3 * CDIM * (CDIM / 2);
        Al = g_Wpl + (size_t)3 * CDIM * (CDIM / 2);
        Bh = g_Oh + (size_t)b * CDIM * (TDIM / 2);
        Bl = g_Ol + (size_t)b * CDIM * (TDIM / 2);
        Od = out + (size_t)b * TDIM * CDIM;
    }
    Ah += (size_t)m0 * (CDIM / 2);
    Al += (size_t)m0 * (CDIM / 2);
    Bh += n0 / 2;
    Bl += n0 / 2;

    int wm = (wid & 1) * 64;
    int wn = (wid >> 1) * 32;

    float d[4][4][4] = {};

    gemm_fill(sb, Ah, Al, Bh, Bl, 0, tid);
    CPA_COMMIT();

    #pragma unroll 1
    for (int s = 0; s < 8; s++) {
        uint32_t sbs = sb + (uint32_t)(s & 1) * STAGE;
        if (s < 7) {
            gemm_fill(sb + (uint32_t)((s + 1) & 1) * STAGE,
                      Ah, Al, Bh, Bl, (s + 1) * 64, tid);
            CPA_COMMIT();
            CPA_WAIT1();
        } else {
            CPA_WAIT0();
        }
        __syncthreads();

        #pragma unroll
        for (int kk = 0; kk < 4; kk++) {
            uint32_t ah[4][4], al[4][4];
            #pragma unroll
            for (int mf = 0; mf < 4; mf++) {
                uint32_t addr = sbs
                    + (uint32_t)((wm + mf * 16 + (lane & 15)) * A_STR_B)
                    + (uint32_t)((kk * 16 + (lane >> 4) * 8) * 2);
                ldsm_x4(addr + SA_HI, ah[mf]);
                ldsm_x4(addr + SA_LO, al[mf]);
            }
            #pragma unroll
            for (int nf2 = 0; nf2 < 2; nf2++) {
                uint32_t baddr = sbs
                    + (uint32_t)((kk * 16 + (lane & 15)) * B_STR_B)
                    + (uint32_t)((wn + nf2 * 16 + (lane >> 4) * 8) * 2);
                uint32_t bh[4], bl[4];
                ldsm_x4t(baddr + SB_HI, bh);
                ldsm_x4t(baddr + SB_LO, bl);
                #pragma unroll
                for (int mf = 0; mf < 4; mf++) {
                    #pragma unroll
                    for (int h = 0; h < 2; h++) {
                        float* dd = d[mf][nf2 * 2 + h];
                        mma_bf16(dd, ah[mf], &bh[h * 2]);
                        mma_bf16(dd, ah[mf], &bl[h * 2]);
                        mma_bf16(dd, al[mf], &bh[h * 2]);
                    }
                }
            }
        }
        __syncthreads();
    }

    int g = lane >> 2, t = lane & 3;
    if (!Od) {
        #pragma unroll
        for (int mf = 0; mf < 4; mf++) {
            int e = m0 + wm + mf * 16 + g;
            #pragma unroll
            for (int nf = 0; nf < 4; nf++) {
                int npair = (n0 + wn + nf * 8) / 2 + t;
                uint32_t hp0, lp0, hp1, lp1;
                split2(d[mf][nf][0], d[mf][nf][1], hp0, lp0);
                split2(d[mf][nf][2], d[mf][nf][3], hp1, lp1);
                size_t ix = cbase + (size_t)e * (TDIM / 2) + npair;
                Ch[ix] = hp0;                  Cl[ix] = lp0;
                Ch[ix + 8 * (TDIM / 2)] = hp1; Cl[ix + 8 * (TDIM / 2)] = lp1;
            }
        }
    } else {
        float* tr = (float*)smem;
        #pragma unroll
        for (int mf = 0; mf < 4; mf++) {
            #pragma unroll
            for (int nf = 0; nf < 4; nf++) {
                int mm = wm + mf * 16 + g;
                int nn = wn + nf * 8 + t * 2;
                tr[(nn + 0) * 132 + mm]     = d[mf][nf][0];
                tr[(nn + 1) * 132 + mm]     = d[mf][nf][1];
                tr[(nn + 0) * 132 + mm + 8] = d[mf][nf][2];
                tr[(nn + 1) * 132 + mm + 8] = d[mf][nf][3];
            }
        }
        __syncthreads();
        int rr = tid >> 1, hh = (tid & 1) * 64;
        float* drow = Od + (size_t)(n0 + rr) * CDIM + m0 + hh;
        const float* bv = bias + m0 + hh;
        #pragma unroll
        for (int j = 0; j < 16; j++) {
            float4 v = *(float4*)&tr[rr * 132 + hh + j * 4];
            v.x += bv[j*4+0]; v.y += bv[j*4+1]; v.z += bv[j*4+2]; v.w += bv[j*4+3];
            *(float4*)(drow + j * 4) = v;
        }
    }
}

// ============================================================================
// HMMA flash attention, 128 threads / 4 warps per CTA, s-block = 64 wide,
// 2 CTAs/SM (88.8 KB smem). R12 winner + Q fragments hoisted to registers:
// Q B-operands loaded once after the preamble (64 regs), scores loop has
// zero Q ldsm. Pipeline unchanged otherwise.
// ============================================================================
#define STR  272
#define QSTR 144
#define SM_QH 0
#define SM_QL 9216
#define SM_KH 18432
#define SM_KL 35840
#define SM_VH 53248
#define SM_VL 70656
#define SM_L  88064
#define SM_RED 88320
#define ATTN_SMEM 88832

__global__ void __launch_bounds__(128) attn_mma(const float* __restrict__ mask)
{
    extern __shared__ char smem[];
    uint32_t sb = smem_u32(smem);
    float* l_sm = (float*)(smem + SM_L);
    float* red  = (float*)(smem + SM_RED);

    int tid = threadIdx.x, wid = tid >> 5, lane = tid & 31;
    int g = lane >> 2, t2 = lane & 3;
    int bh = blockIdx.y, s0 = blockIdx.x * 64;
    int wt  = (wid & 1) * 64;      // t-half
    int wss = (wid >> 1) * 32;     // s-group (2 groups x 32s)

    const uint32_t* Kh = g_Kh + (size_t)bh * HKT;
    const uint32_t* Kl = g_Kl + (size_t)bh * HKT;
    const uint32_t* Vh = g_Vh + (size_t)bh * HKT;
    const uint32_t* Vl = g_Vl + (size_t)bh * HKT;
    const uint32_t* Qh = g_Qh + (size_t)bh * HKT;
    const uint32_t* Ql = g_Ql + (size_t)bh * HKT;

    // ---- preamble: Q (64k x 64s) + K(0) in one group
    #pragma unroll
    for (int q = 0; q < 4; q++) {
        int idx = q * 128 + tid, r = idx >> 3, c = idx & 7;
        uint32_t so = (uint32_t)(r * QSTR + c * 16);
        const size_t qix = (size_t)r * (TDIM / 2) + s0 / 2 + c * 4;
        cpa16(sb + SM_QH + so, Qh + qix);
        cpa16(sb + SM_QL + so, Ql + qix);
    }
    #pragma unroll
    for (int q = 0; q < 8; q++) {
        int idx = q * 128 + tid, r = idx >> 4, c16 = idx & 15;
        uint32_t so = (uint32_t)(r * STR + c16 * 16);
        const size_t kix = (size_t)r * (TDIM / 2) + c16 * 4;
        cpa16(sb + SM_KH + so, Kh + kix);
        cpa16(sb + SM_KL + so, Kl + kix);
    }
    CPA_COMMIT();

    // ---- hoist Q B-fragments into registers (once for all 16 tiles)
    CPA_WAIT0();
    __syncthreads();
    uint32_t qbh[4][2][4], qbl[4][2][4];
    #pragma unroll
    for (int kk = 0; kk < 4; kk++) {
        #pragma unroll
        for (int nf2 = 0; nf2 < 2; nf2++) {
            uint32_t br = sb
                + (uint32_t)((kk * 16 + (lane & 15)) * QSTR)
                + (uint32_t)((wss + nf2 * 16 + ((lane >> 4) << 3)) * 2);
            ldsm_x4t(br + SM_QH, qbh[kk][nf2]);
            ldsm_x4t(br + SM_QL, qbl[kk][nf2]);
        }
    }

    float o[4][4][4] = {};        // partial O: [vf(16v)][nf(8s)][frags]
    float lacc[8];
    #pragma unroll
    for (int j = 0; j < 8; j++) lacc[j] = 0.0f;

    #pragma unroll 1
    for (int t0 = 0; t0 < TDIM; t0 += 128) {
        int tpn = ((t0 + 128) & (TDIM - 1)) / 2;

        CPA_WAIT0();       // K(t) landed
        __syncthreads();   // prev PV done reading V; K visible

        // issue V(t)
        #pragma unroll
        for (int q = 0; q < 8; q++) {
            int idx = q * 128 + tid, r = idx >> 4, c16 = idx & 15;
            uint32_t so = (uint32_t)(r * STR + c16 * 16);
            const size_t gix = (size_t)r * (TDIM / 2) + t0 / 2 + c16 * 4;
            cpa16(sb + SM_VH + so, Vh + gix);
            cpa16(sb + SM_VL + so, Vl + gix);
        }
        CPA_COMMIT();

        // ---- scores: S[t][s] = K^T Q over warp tile 64t x 32s (Q from regs)
        float sc[4][4][4] = {};
        #pragma unroll
        for (int kk = 0; kk < 4; kk++) {
            uint32_t ah[4][4], al[4][4];
            #pragma unroll
            for (int mf = 0; mf < 4; mf++) {
                uint32_t ar = sb
                    + (uint32_t)((kk * 16 + (lane & 7) + ((lane >> 4) << 3)) * STR)
                    + (uint32_t)((wt + mf * 16 + (((lane >> 3) & 1) << 3)) * 2);
                ldsm_x4t(ar + SM_KH, ah[mf]);
                ldsm_x4t(ar + SM_KL, al[mf]);
            }
            #pragma unroll
            for (int nf2 = 0; nf2 < 2; nf2++) {
                #pragma unroll
                for (int mf = 0; mf < 4; mf++) {
                    #pragma unroll
                    for (int h = 0; h < 2; h++) {
                        float* dd = sc[mf][nf2 * 2 + h];
                        mma_bf16(dd, ah[mf], &qbh[kk][nf2][h * 2]);
                        mma_bf16(dd, ah[mf], &qbl[kk][nf2][h * 2]);
                        mma_bf16(dd, al[mf], &qbh[kk][nf2][h * 2]);
                    }
                }
            }
        }

        // ---- mask (direct LDG) + exp2 on MUFU, l in regs
        #pragma unroll
        for (int mf = 0; mf < 4; mf++) {
            #pragma unroll
            for (int j2 = 0; j2 < 2; j2++) {
                int tl = wt + mf * 16 + g + j2 * 8;
                const float* mrow = mask + (size_t)(t0 + tl) * TDIM + s0 + wss;
                #pragma unroll
                for (int nf = 0; nf < 4; nf++) {
                    float2 mk = *(const float2*)(mrow + nf * 8 + t2 * 2);
                    float e0 = ex2a((sc[mf][nf][j2 * 2 + 0] + mk.x) * C_EXP8);
                    float e1 = ex2a((sc[mf][nf][j2 * 2 + 1] + mk.y) * C_EXP8);
                    sc[mf][nf][j2 * 2 + 0] = e0;
                    sc[mf][nf][j2 * 2 + 1] = e1;
                    lacc[nf * 2 + 0] += e0;
                    lacc[nf * 2 + 1] += e1;
                }
            }
        }
        __syncthreads();   // all warps done reading K(t)

        // issue K(t+1) — stays in flight through PV
        #pragma unroll
        for (int q = 0; q < 8; q++) {
            int idx = q * 128 + tid, r = idx >> 4, c16 = idx & 15;
            uint32_t so = (uint32_t)(r * STR + c16 * 16);
            const size_t gix = (size_t)r * (TDIM / 2) + tpn + c16 * 4;
            cpa16(sb + SM_KH + so, Kh + gix);
            cpa16(sb + SM_KL + so, Kl + gix);
        }
        CPA_COMMIT();
        CPA_WAIT1();       // drain V(t); keep K(t+1) in flight
        __syncthreads();   // V(t) visible

        // ---- PV: O[v][s] += V[v][t] * P[t][s]; P from registers via movmatrix
        #pragma unroll
        for (int kb = 0; kb < 4; kb++) {
            uint32_t Bh[8], Bl[8];
            #pragma unroll
            for (int nf = 0; nf < 4; nf++) {
                uint32_t h0, l0, h1, l1;
                split2(sc[kb][nf][0], sc[kb][nf][1], h0, l0);
                split2(sc[kb][nf][2], sc[kb][nf][3], h1, l1);
                Bh[nf * 2 + 0] = movm(h0);  Bh[nf * 2 + 1] = movm(h1);
                Bl[nf * 2 + 0] = movm(l0);  Bl[nf * 2 + 1] = movm(l1);
            }
            #pragma unroll
            for (int vf = 0; vf < 4; vf++) {
                uint32_t ar = sb
                    + (uint32_t)((vf * 16 + (lane & 15)) * STR)
                    + (uint32_t)((wt + kb * 16 + ((lane >> 4) << 3)) * 2);
                uint32_t avh[4], avl[4];
                ldsm_x4(ar + SM_VH, avh);
                ldsm_x4(ar + SM_VL, avl);
                #pragma unroll
                for (int nf = 0; nf < 4; nf++) {
                    float* dd = o[vf][nf];
                    mma_bf16(dd, avh, &Bh[nf * 2]);
                    mma_bf16(dd, avh, &Bl[nf * 2]);
                    mma_bf16(dd, avl, &Bh[nf * 2]);
                }
            }
        }
    }

    // ---- epilogue
    CPA_WAIT0();           // drain trailing K prefetch before reusing smem
    __syncthreads();

    #pragma unroll
    for (int j = 0; j < 8; j++) {
        lacc[j] += __shfl_xor_sync(0xffffffffu, lacc[j], 4);
        lacc[j] += __shfl_xor_sync(0xffffffffu, lacc[j], 8);
        lacc[j] += __shfl_xor_sync(0xffffffffu, lacc[j], 16);
    }
    if (g == 0) {
        #pragma unroll
        for (int nf = 0; nf < 4; nf++) {
            red[(wid & 1) * 64 + wss + nf * 8 + t2 * 2 + 0] = lacc[nf * 2 + 0];
            red[(wid & 1) * 64 + wss + nf * 8 + t2 * 2 + 1] = lacc[nf * 2 + 1];
        }
    }
    // store O partials per warp: [v(64)][s_local(32)] fp32 (32 KB total)
    float* part = (float*)smem;
    {
        float* pw = part + wid * 2048;
        #pragma unroll
        for (int vf = 0; vf < 4; vf++) {
            #pragma unroll
            for (int nf = 0; nf < 4; nf++) {
                int v = vf * 16 + g, sl = nf * 8 + t2 * 2;
                pw[(v + 0) * 32 + sl]     = o[vf][nf][0];
                pw[(v + 0) * 32 + sl + 1] = o[vf][nf][1];
                pw[(v + 8) * 32 + sl]     = o[vf][nf][2];
                pw[(v + 8) * 32 + sl + 1] = o[vf][nf][3];
            }
        }
    }
    __syncthreads();
    if (tid < 64) l_sm[tid] = red[tid] + red[64 + tid];
    __syncthreads();

    // final: sum 2 t-half partials, normalize, pack, store
    uint32_t* Ohp = g_Oh + (size_t)bh * DK * (TDIM / 2);
    uint32_t* Olp = g_Ol + (size_t)bh * DK * (TDIM / 2);
    int v = tid >> 1;
    #pragma unroll
    for (int j = 0; j < 16; j++) {
        int sp = (tid & 1) * 16 + j;          // s pair index 0..31
        int s  = sp * 2;
        int sg = s >> 5;                       // s-group (0/1)
        const float* r0 = part + (sg * 2 + 0) * 2048 + v * 32;
        const float* r1 = part + (sg * 2 + 1) * 2048 + v * 32;
        int sl = s & 31;
        float f0 = (r0[sl]     + r1[sl])     / l_sm[s];
        float f1 = (r0[sl + 1] + r1[sl + 1]) / l_sm[s + 1];
        uint32_t hp, lp; split2(f0, f1, hp, lp);
        size_t ix = (size_t)v * (TDIM / 2) + s0 / 2 + sp;
        Ohp[ix] = hp; Olp[ix] = lp;
    }
}

// ---------------------------------------------------------------------------
extern "C" void kernel_launch(void* const* d_in, const int* in_sizes, int n_in,
                              void* d_out, int out_size)
{
    const float* x    = (const float*)d_in[0];
    const float* y    = (const float*)d_in[1];
    const float* mask = (const float*)d_in[2];
    const float* Wk   = (const float*)d_in[3];
    const float* Wv   = (const float*)d_in[4];
    const float* Wq   = (const float*)d_in[5];
    const float* W    = (const float*)d_in[6];
    const float* bias = (const float*)d_in[7];
    float* out = (float*)d_out;

    cudaFuncSetAttribute(gemm_mma, cudaFuncAttributeMaxDynamicSharedMemorySize,
                         GEMM_SMEM);
    cudaFuncSetAttribute(attn_mma, cudaFuncAttributeMaxDynamicSharedMemorySize,
                         ATTN_SMEM);

    // 0) split all fp32 inputs into packed bf16 hi/lo
    prep_split<<<PREP_THREADS / 256, 256>>>(x, y, Wk, Wv, Wq, W);
    // 1) K,V,Q projections — R12 config (z = proj*2 + batch)
    gemm_mma<<<dim3(16, 4, 6), 256, GEMM_SMEM>>>(bias, out, 0);
    // 2) HMMA flash attention — R12 + Q-in-registers
    attn_mma<<<dim3(32, NBH), 128, ATTN_SMEM>>>(mask);
    // 3) output projection + bias — R12 config
    gemm_mma<<<dim3(16, 4, 2), 256, GEMM_SMEM>>>(bias, out, 6);
}

// round 15
// speedup vs baseline: 1.0712x; 1.0712x over previous
#include <cuda_runtime.h>
#include <cuda_bf16.h>
#include <math.h>
#include <stdint.h>

// Shapes (fixed by the problem)
#define TDIM 2048   // T == S
#define CDIM 512    // I == O == E == Ev
#define BB   2
#define NBH  16     // B*H
#define DK   64     // KEY_DIM == VALUE_DIM
#define HKT  (DK * TDIM / 2)      // uint32 (bf16x2) per bh plane

// Pre-split bf16 hi/lo packed (bf16x2 along the fast axis) device scratch.
__device__ uint32_t g_Kh[NBH * HKT], g_Kl[NBH * HKT];
__device__ uint32_t g_Vh[NBH * HKT], g_Vl[NBH * HKT];
__device__ uint32_t g_Qh[NBH * HKT], g_Ql[NBH * HKT];
__device__ uint32_t g_Oh[BB * CDIM * TDIM / 2], g_Ol[BB * CDIM * TDIM / 2];
__device__ uint32_t g_Xh[BB * CDIM * TDIM / 2], g_Xl[BB * CDIM * TDIM / 2];
__device__ uint32_t g_Yh[BB * CDIM * TDIM / 2], g_Yl[BB * CDIM * TDIM / 2];
__device__ uint32_t g_Wph[4 * CDIM * CDIM / 2], g_Wpl[4 * CDIM * CDIM / 2];

// ============================================================================
// Warp-MMA helpers (baseline PTX: works on plain sm_103 target)
// ============================================================================
__device__ __forceinline__ uint32_t smem_u32(const void* p) {
    uint32_t a;
    asm("{ .reg .u64 t; cvta.to.shared.u64 t, %1; cvt.u32.u64 %0, t; }"
        : "=r"(a) : "l"(p));
    return a;
}
__device__ __forceinline__ void ldsm_x4(uint32_t addr, uint32_t* r) {
    asm volatile("ldmatrix.sync.aligned.m8n8.x4.shared.b16 {%0,%1,%2,%3}, [%4];"
                 : "=r"(r[0]), "=r"(r[1]), "=r"(r[2]), "=r"(r[3]) : "r"(addr));
}
__device__ __forceinline__ void ldsm_x4t(uint32_t addr, uint32_t* r) {
    asm volatile("ldmatrix.sync.aligned.m8n8.x4.trans.shared.b16 {%0,%1,%2,%3}, [%4];"
                 : "=r"(r[0]), "=r"(r[1]), "=r"(r[2]), "=r"(r[3]) : "r"(addr));
}
__device__ __forceinline__ uint32_t movm(uint32_t s) {
    uint32_t d;
    asm volatile("movmatrix.sync.aligned.m8n8.trans.b16 %0, %1;"
                 : "=r"(d) : "r"(s));
    return d;
}
__device__ __forceinline__ void mma_bf16(float* d, const uint32_t* a,
                                         const uint32_t* b) {
    asm volatile(
        "mma.sync.aligned.m16n8k16.row.col.f32.bf16.bf16.f32 "
        "{%0,%1,%2,%3}, {%4,%5,%6,%7}, {%8,%9}, {%0,%1,%2,%3};"
        : "+f"(d[0]), "+f"(d[1]), "+f"(d[2]), "+f"(d[3])
        : "r"(a[0]), "r"(a[1]), "r"(a[2]), "r"(a[3]), "r"(b[0]), "r"(b[1]));
}
__device__ __forceinline__ void cpa16(uint32_t smem_dst, const void* gsrc) {
    asm volatile("cp.async.cg.shared.global [%0], [%1], 16;"
                 :: "r"(smem_dst), "l"(gsrc));
}
#define CPA_COMMIT() asm volatile("cp.async.commit_group;" ::: "memory")
#define CPA_WAIT0()  asm volatile("cp.async.wait_group 0;" ::: "memory")
#define CPA_WAIT1()  asm volatile("cp.async.wait_group 1;" ::: "memory")

__device__ __forceinline__ uint32_t pack2(float lo, float hi) {
    uint32_t r;
    asm("cvt.rn.bf16x2.f32 %0, %1, %2;" : "=r"(r) : "f"(hi), "f"(lo));
    return r;
}
__device__ __forceinline__ void split2(float a, float b, uint32_t& hi, uint32_t& lo) {
    hi = pack2(a, b);
    float ha = __int_as_float(hi << 16);
    float hb = __int_as_float(hi & 0xffff0000u);
    lo = pack2(a - ha, b - hb);
}
__device__ __forceinline__ void split4(float4 v, uint2& hi, uint2& lo) {
    split2(v.x, v.y, hi.x, lo.x);
    split2(v.z, v.w, hi.y, lo.y);
}

// MUFU-pipe exp2 (tensor cores own GEMMs; MUFU is otherwise idle)
__device__ __forceinline__ float ex2a(float x) {
    float y;
    asm("ex2.approx.f32 %0, %1;" : "=f"(y) : "f"(x));
    return y;
}
#define C_EXP8 0.18033688f   // log2(e) / 8

// ============================================================================
// Prep: split x, y, and all weights into packed bf16 hi/lo
// ============================================================================
#define PREP_THREADS (524288 * 2 + 4 * 65536)   // 1,310,720

__global__ void __launch_bounds__(256) prep_split(
    const float* __restrict__ x, const float* __restrict__ y,
    const float* __restrict__ Wk, const float* __restrict__ Wv,
    const float* __restrict__ Wq, const float* __restrict__ Wf)
{
    int idx = blockIdx.x * 256 + threadIdx.x;
    const float* src; uint32_t* dh; uint32_t* dl; size_t off, dst;
    if (idx < 524288) {
        src = x; dh = g_Xh; dl = g_Xl; off = idx; dst = (size_t)idx * 2;
    } else if (idx < 1048576) {
        int w = idx - 524288;
        src = y; dh = g_Yh; dl = g_Yl; off = w; dst = (size_t)w * 2;
    } else {
        int w = idx - 1048576;
        int pj = w >> 16, loc = w & 65535;
        src = (pj == 0) ? Wk : (pj == 1) ? Wv : (pj == 2) ? Wq : Wf;
        dh = g_Wph; dl = g_Wpl; off = loc; dst = (size_t)w * 2;
    }
    float4 v = *(const float4*)(src + off * 4);
    uint2 hi, lo; split4(v, hi, lo);
    dh[dst] = hi.x; dh[dst + 1] = hi.y;
    dl[dst] = lo.x; dl[dst + 1] = lo.y;
}

// ============================================================================
// bf16x3 HMMA GEMM (R12 measured-best: 256 threads, 8 warps 64m x 32n)
// ============================================================================
#define A_STR_B 144
#define B_STR_B 272
#define SA_HI 0
#define SA_LO 18432
#define SB_HI 36864
#define SB_LO 54272
#define STAGE 71680
#define GEMM_SMEM (2 * STAGE)

__device__ __forceinline__ void gemm_fill(uint32_t sbs, const uint32_t* Ah,
                                          const uint32_t* Al, const uint32_t* Bh,
                                          const uint32_t* Bl, int k0, int tid) {
    #pragma unroll
    for (int q = 0; q < 4; q++) {
        int idx = q * 256 + tid, r = idx >> 3, c = idx & 7;
        uint32_t so = (uint32_t)(r * A_STR_B + c * 16);
        size_t gi = (size_t)r * (CDIM / 2) + k0 / 2 + c * 4;
        cpa16(sbs + SA_HI + so, Ah + gi);
        cpa16(sbs + SA_LO + so, Al + gi);
    }
    #pragma unroll
    for (int q = 0; q < 4; q++) {
        int idx = q * 256 + tid, r = idx >> 4, c = idx & 15;
        uint32_t so = (uint32_t)(r * B_STR_B + c * 16);
        size_t gi = (size_t)(k0 + r) * (TDIM / 2) + c * 4;
        cpa16(sbs + SB_HI + so, Bh + gi);
        cpa16(sbs + SB_LO + so, Bl + gi);
    }
}

__global__ void __launch_bounds__(256, 1) gemm_mma(
    const float* __restrict__ bias, float* __restrict__ out, int zbase)
{
    extern __shared__ char smem[];
    uint32_t sb = smem_u32(smem);
    int tid = threadIdx.x, wid = tid >> 5, lane = tid & 31;

    int z = blockIdx.z + zbase;
    int m0 = blockIdx.y * 128, n0 = blockIdx.x * 128;
    const uint32_t *Ah, *Al, *Bh, *Bl;
    uint32_t *Ch = nullptr, *Cl = nullptr;
    float* Od = nullptr;
    size_t cbase = 0;
    if (z < 6) {
        int proj = z >> 1, b = z & 1;
        Ah = g_Wph + (size_t)proj * CDIM * (CDIM / 2);
        Al = g_Wpl + (size_t)proj * CDIM * (CDIM / 2);
        const uint32_t* Xh = (proj == 2) ? g_Yh : g_Xh;
        const uint32_t* Xl = (proj == 2) ? g_Yl : g_Xl;
        Bh = Xh + (size_t)b * CDIM * (TDIM / 2);
        Bl = Xl + (size_t)b * CDIM * (TDIM / 2);
        Ch = (proj == 0) ? g_Kh : (proj == 1) ? g_Vh : g_Qh;
        Cl = (proj == 0) ? g_Kl : (proj == 1) ? g_Vl : g_Ql;
        cbase = (size_t)b * CDIM * (TDIM / 2);
    } else {
        int b = z - 6;
        Ah = g_Wph + (size_t)3 * CDIM * (CDIM / 2);
        Al = g_Wpl + (size_t)3 * CDIM * (CDIM / 2);
        Bh = g_Oh + (size_t)b * CDIM * (TDIM / 2);
        Bl = g_Ol + (size_t)b * CDIM * (TDIM / 2);
        Od = out + (size_t)b * TDIM * CDIM;
    }
    Ah += (size_t)m0 * (CDIM / 2);
    Al += (size_t)m0 * (CDIM / 2);
    Bh += n0 / 2;
    Bl += n0 / 2;

    int wm = (wid & 1) * 64;
    int wn = (wid >> 1) * 32;

    float d[4][4][4] = {};

    gemm_fill(sb, Ah, Al, Bh, Bl, 0, tid);
    CPA_COMMIT();

    #pragma unroll 1
    for (int s = 0; s < 8; s++) {
        uint32_t sbs = sb + (uint32_t)(s & 1) * STAGE;
        if (s < 7) {
            gemm_fill(sb + (uint32_t)((s + 1) & 1) * STAGE,
                      Ah, Al, Bh, Bl, (s + 1) * 64, tid);
            CPA_COMMIT();
            CPA_WAIT1();
        } else {
            CPA_WAIT0();
        }
        __syncthreads();

        #pragma unroll
        for (int kk = 0; kk < 4; kk++) {
            uint32_t ah[4][4], al[4][4];
            #pragma unroll
            for (int mf = 0; mf < 4; mf++) {
                uint32_t addr = sbs
                    + (uint32_t)((wm + mf * 16 + (lane & 15)) * A_STR_B)
                    + (uint32_t)((kk * 16 + (lane >> 4) * 8) * 2);
                ldsm_x4(addr + SA_HI, ah[mf]);
                ldsm_x4(addr + SA_LO, al[mf]);
            }
            #pragma unroll
            for (int nf2 = 0; nf2 < 2; nf2++) {
                uint32_t baddr = sbs
                    + (uint32_t)((kk * 16 + (lane & 15)) * B_STR_B)
                    + (uint32_t)((wn + nf2 * 16 + (lane >> 4) * 8) * 2);
                uint32_t bh[4], bl[4];
                ldsm_x4t(baddr + SB_HI, bh);
                ldsm_x4t(baddr + SB_LO, bl);
                #pragma unroll
                for (int mf = 0; mf < 4; mf++) {
                    #pragma unroll
                    for (int h = 0; h < 2; h++) {
                        float* dd = d[mf][nf2 * 2 + h];
                        mma_bf16(dd, ah[mf], &bh[h * 2]);
                        mma_bf16(dd, ah[mf], &bl[h * 2]);
                        mma_bf16(dd, al[mf], &bh[h * 2]);
                    }
                }
            }
        }
        __syncthreads();
    }

    int g = lane >> 2, t = lane & 3;
    if (!Od) {
        #pragma unroll
        for (int mf = 0; mf < 4; mf++) {
            int e = m0 + wm + mf * 16 + g;
            #pragma unroll
            for (int nf = 0; nf < 4; nf++) {
                int npair = (n0 + wn + nf * 8) / 2 + t;
                uint32_t hp0, lp0, hp1, lp1;
                split2(d[mf][nf][0], d[mf][nf][1], hp0, lp0);
                split2(d[mf][nf][2], d[mf][nf][3], hp1, lp1);
                size_t ix = cbase + (size_t)e * (TDIM / 2) + npair;
                Ch[ix] = hp0;                  Cl[ix] = lp0;
                Ch[ix + 8 * (TDIM / 2)] = hp1; Cl[ix + 8 * (TDIM / 2)] = lp1;
            }
        }
    } else {
        float* tr = (float*)smem;
        #pragma unroll
        for (int mf = 0; mf < 4; mf++) {
            #pragma unroll
            for (int nf = 0; nf < 4; nf++) {
                int mm = wm + mf * 16 + g;
                int nn = wn + nf * 8 + t * 2;
                tr[(nn + 0) * 132 + mm]     = d[mf][nf][0];
                tr[(nn + 1) * 132 + mm]     = d[mf][nf][1];
                tr[(nn + 0) * 132 + mm + 8] = d[mf][nf][2];
                tr[(nn + 1) * 132 + mm + 8] = d[mf][nf][3];
            }
        }
        __syncthreads();
        int rr = tid >> 1, hh = (tid & 1) * 64;
        float* drow = Od + (size_t)(n0 + rr) * CDIM + m0 + hh;
        const float* bv = bias + m0 + hh;
        #pragma unroll
        for (int j = 0; j < 16; j++) {
            float4 v = *(float4*)&tr[rr * 132 + hh + j * 4];
            v.x += bv[j*4+0]; v.y += bv[j*4+1]; v.z += bv[j*4+2]; v.w += bv[j*4+3];
            *(float4*)(drow + j * 4) = v;
        }
    }
}

// ============================================================================
// HMMA flash attention, 128 threads / 4 warps per CTA, s-block = 64 wide.
// (R12 measured-best configuration, verbatim.)
// ============================================================================
#define STR  272
#define QSTR 144
#define SM_QH 0
#define SM_QL 9216
#define SM_KH 18432
#define SM_KL 35840
#define SM_VH 53248
#define SM_VL 70656
#define SM_L  88064
#define SM_RED 88320
#define ATTN_SMEM 88832

__global__ void __launch_bounds__(128) attn_mma(const float* __restrict__ mask)
{
    extern __shared__ char smem[];
    uint32_t sb = smem_u32(smem);
    float* l_sm = (float*)(smem + SM_L);
    float* red  = (float*)(smem + SM_RED);

    int tid = threadIdx.x, wid = tid >> 5, lane = tid & 31;
    int g = lane >> 2, t2 = lane & 3;
    int bh = blockIdx.y, s0 = blockIdx.x * 64;
    int wt  = (wid & 1) * 64;      // t-half
    int wss = (wid >> 1) * 32;     // s-group (2 groups x 32s)

    const uint32_t* Kh = g_Kh + (size_t)bh * HKT;
    const uint32_t* Kl = g_Kl + (size_t)bh * HKT;
    const uint32_t* Vh = g_Vh + (size_t)bh * HKT;
    const uint32_t* Vl = g_Vl + (size_t)bh * HKT;
    const uint32_t* Qh = g_Qh + (size_t)bh * HKT;
    const uint32_t* Ql = g_Ql + (size_t)bh * HKT;

    // ---- preamble: Q (64k x 64s) + K(0) in one group
    #pragma unroll
    for (int q = 0; q < 4; q++) {
        int idx = q * 128 + tid, r = idx >> 3, c = idx & 7;
        uint32_t so = (uint32_t)(r * QSTR + c * 16);
        const size_t qix = (size_t)r * (TDIM / 2) + s0 / 2 + c * 4;
        cpa16(sb + SM_QH + so, Qh + qix);
        cpa16(sb + SM_QL + so, Ql + qix);
    }
    #pragma unroll
    for (int q = 0; q < 8; q++) {
        int idx = q * 128 + tid, r = idx >> 4, c16 = idx & 15;
        uint32_t so = (uint32_t)(r * STR + c16 * 16);
        const size_t kix = (size_t)r * (TDIM / 2) + c16 * 4;
        cpa16(sb + SM_KH + so, Kh + kix);
        cpa16(sb + SM_KL + so, Kl + kix);
    }
    CPA_COMMIT();

    float o[4][4][4] = {};        // partial O: [vf(16v)][nf(8s)][frags]
    float lacc[8];
    #pragma unroll
    for (int j = 0; j < 8; j++) lacc[j] = 0.0f;

    #pragma unroll 1
    for (int t0 = 0; t0 < TDIM; t0 += 128) {
        int tpn = ((t0 + 128) & (TDIM - 1)) / 2;

        CPA_WAIT0();       // K(t) landed
        __syncthreads();   // prev PV done reading V; K visible

        // issue V(t)
        #pragma unroll
        for (int q = 0; q < 8; q++) {
            int idx = q * 128 + tid, r = idx >> 4, c16 = idx & 15;
            uint32_t so = (uint32_t)(r * STR + c16 * 16);
            const size_t gix = (size_t)r * (TDIM / 2) + t0 / 2 + c16 * 4;
            cpa16(sb + SM_VH + so, Vh + gix);
            cpa16(sb + SM_VL + so, Vl + gix);
        }
        CPA_COMMIT();

        // ---- scores: S[t][s] = K^T Q over warp tile 64t x 32s
        float sc[4][4][4] = {};
        #pragma unroll
        for (int kk = 0; kk < 4; kk++) {
            uint32_t ah[4][4], al[4][4];
            #pragma unroll
            for (int mf = 0; mf < 4; mf++) {
                uint32_t ar = sb
                    + (uint32_t)((kk * 16 + (lane & 7) + ((lane >> 4) << 3)) * STR)
                    + (uint32_t)((wt + mf * 16 + (((lane >> 3) & 1) << 3)) * 2);
                ldsm_x4t(ar + SM_KH, ah[mf]);
                ldsm_x4t(ar + SM_KL, al[mf]);
            }
            #pragma unroll
            for (int nf2 = 0; nf2 < 2; nf2++) {
                uint32_t br = sb
                    + (uint32_t)((kk * 16 + (lane & 15)) * QSTR)
                    + (uint32_t)((wss + nf2 * 16 + ((lane >> 4) << 3)) * 2);
                uint32_t bh4[4], bl4[4];
                ldsm_x4t(br + SM_QH, bh4);
                ldsm_x4t(br + SM_QL, bl4);
                #pragma unroll
                for (int mf = 0; mf < 4; mf++) {
                    #pragma unroll
                    for (int h = 0; h < 2; h++) {
                        float* dd = sc[mf][nf2 * 2 + h];
                        mma_bf16(dd, ah[mf], &bh4[h * 2]);
                        mma_bf16(dd, ah[mf], &bl4[h * 2]);
                        mma_bf16(dd, al[mf], &bh4[h * 2]);
                    }
                }
            }
        }

        // ---- mask (direct LDG) + exp2 on MUFU, l in regs
        #pragma unroll
        for (int mf = 0; mf < 4; mf++) {
            #pragma unroll
            for (int j2 = 0; j2 < 2; j2++) {
                int tl = wt + mf * 16 + g + j2 * 8;
                const float* mrow = mask + (size_t)(t0 + tl) * TDIM + s0 + wss;
                #pragma unroll
                for (int nf = 0; nf < 4; nf++) {
                    float2 mk = *(const float2*)(mrow + nf * 8 + t2 * 2);
                    float e0 = ex2a((sc[mf][nf][j2 * 2 + 0] + mk.x) * C_EXP8);
                    float e1 = ex2a((sc[mf][nf][j2 * 2 + 1] + mk.y) * C_EXP8);
                    sc[mf][nf][j2 * 2 + 0] = e0;
                    sc[mf][nf][j2 * 2 + 1] = e1;
                    lacc[nf * 2 + 0] += e0;
                    lacc[nf * 2 + 1] += e1;
                }
            }
        }
        __syncthreads();   // all warps done reading K(t)

        // issue K(t+1) — stays in flight through PV
        #pragma unroll
        for (int q = 0; q < 8; q++) {
            int idx = q * 128 + tid, r = idx >> 4, c16 = idx & 15;
            uint32_t so = (uint32_t)(r * STR + c16 * 16);
            const size_t gix = (size_t)r * (TDIM / 2) + tpn + c16 * 4;
            cpa16(sb + SM_KH + so, Kh + gix);
            cpa16(sb + SM_KL + so, Kl + gix);
        }
        CPA_COMMIT();
        CPA_WAIT1();       // drain V(t); keep K(t+1) in flight
        __syncthreads();   // V(t) visible

        // ---- PV: O[v][s] += V[v][t] * P[t][s]; P from registers via movmatrix
        #pragma unroll
        for (int kb = 0; kb < 4; kb++) {
            uint32_t Bh[8], Bl[8];
            #pragma unroll
            for (int nf = 0; nf < 4; nf++) {
                uint32_t h0, l0, h1, l1;
                split2(sc[kb][nf][0], sc[kb][nf][1], h0, l0);
                split2(sc[kb][nf][2], sc[kb][nf][3], h1, l1);
                Bh[nf * 2 + 0] = movm(h0);  Bh[nf * 2 + 1] = movm(h1);
                Bl[nf * 2 + 0] = movm(l0);  Bl[nf * 2 + 1] = movm(l1);
            }
            #pragma unroll
            for (int vf = 0; vf < 4; vf++) {
                uint32_t ar = sb
                    + (uint32_t)((vf * 16 + (lane & 15)) * STR)
                    + (uint32_t)((wt + kb * 16 + ((lane >> 4) << 3)) * 2);
                uint32_t avh[4], avl[4];
                ldsm_x4(ar + SM_VH, avh);
                ldsm_x4(ar + SM_VL, avl);
                #pragma unroll
                for (int nf = 0; nf < 4; nf++) {
                    float* dd = o[vf][nf];
                    mma_bf16(dd, avh, &Bh[nf * 2]);
                    mma_bf16(dd, avh, &Bl[nf * 2]);
                    mma_bf16(dd, avl, &Bh[nf * 2]);
                }
            }
        }
    }

    // ---- epilogue
    CPA_WAIT0();           // drain trailing K prefetch before reusing smem
    __syncthreads();

    #pragma unroll
    for (int j = 0; j < 8; j++) {
        lacc[j] += __shfl_xor_sync(0xffffffffu, lacc[j], 4);
        lacc[j] += __shfl_xor_sync(0xffffffffu, lacc[j], 8);
        lacc[j] += __shfl_xor_sync(0xffffffffu, lacc[j], 16);
    }
    if (g == 0) {
        #pragma unroll
        for (int nf = 0; nf < 4; nf++) {
            red[(wid & 1) * 64 + wss + nf * 8 + t2 * 2 + 0] = lacc[nf * 2 + 0];
            red[(wid & 1) * 64 + wss + nf * 8 + t2 * 2 + 1] = lacc[nf * 2 + 1];
        }
    }
    // store O partials per warp: [v(64)][s_local(32)] fp32 (32 KB total)
    float* part = (float*)smem;
    {
        float* pw = part + wid * 2048;
        #pragma unroll
        for (int vf = 0; vf < 4; vf++) {
            #pragma unroll
            for (int nf = 0; nf < 4; nf++) {
                int v = vf * 16 + g, sl = nf * 8 + t2 * 2;
                pw[(v + 0) * 32 + sl]     = o[vf][nf][0];
                pw[(v + 0) * 32 + sl + 1] = o[vf][nf][1];
                pw[(v + 8) * 32 + sl]     = o[vf][nf][2];
                pw[(v + 8) * 32 + sl + 1] = o[vf][nf][3];
            }
        }
    }
    __syncthreads();
    if (tid < 64) l_sm[tid] = red[tid] + red[64 + tid];
    __syncthreads();

    // final: sum 2 t-half partials, normalize, pack, store
    uint32_t* Ohp = g_Oh + (size_t)bh * DK * (TDIM / 2);
    uint32_t* Olp = g_Ol + (size_t)bh * DK * (TDIM / 2);
    int v = tid >> 1;
    #pragma unroll
    for (int j = 0; j < 16; j++) {
        int sp = (tid & 1) * 16 + j;          // s pair index 0..31
        int s  = sp * 2;
        int sg = s >> 5;                       // s-group (0/1)
        const float* r0 = part + (sg * 2 + 0) * 2048 + v * 32;
        const float* r1 = part + (sg * 2 + 1) * 2048 + v * 32;
        int sl = s & 31;
        float f0 = (r0[sl]     + r1[sl])     / l_sm[s];
        float f1 = (r0[sl + 1] + r1[sl + 1]) / l_sm[s + 1];
        uint32_t hp, lp; split2(f0, f1, hp, lp);
        size_t ix = (size_t)v * (TDIM / 2) + s0 / 2 + sp;
        Ohp[ix] = hp; Olp[ix] = lp;
    }
}

// ---------------------------------------------------------------------------
extern "C" void kernel_launch(void* const* d_in, const int* in_sizes, int n_in,
                              void* d_out, int out_size)
{
    const float* x    = (const float*)d_in[0];
    const float* y    = (const float*)d_in[1];
    const float* mask = (const float*)d_in[2];
    const float* Wk   = (const float*)d_in[3];
    const float* Wv   = (const float*)d_in[4];
    const float* Wq   = (const float*)d_in[5];
    const float* W    = (const float*)d_in[6];
    const float* bias = (const float*)d_in[7];
    float* out = (float*)d_out;

    cudaFuncSetAttribute(gemm_mma, cudaFuncAttributeMaxDynamicSharedMemorySize,
                         GEMM_SMEM);
    cudaFuncSetAttribute(attn_mma, cudaFuncAttributeMaxDynamicSharedMemorySize,
                         ATTN_SMEM);

    // 0) split all fp32 inputs into packed bf16 hi/lo
    prep_split<<<PREP_THREADS / 256, 256>>>(x, y, Wk, Wv, Wq, W);
    // 1) K,V,Q projections — R12 config (z = proj*2 + batch)
    gemm_mma<<<dim3(16, 4, 6), 256, GEMM_SMEM>>>(bias, out, 0);
    // 2) HMMA flash attention — R12 config (2 CTAs/SM)
    attn_mma<<<dim3(32, NBH), 128, ATTN_SMEM>>>(mask);
    // 3) output projection + bias — R12 config
    gemm_mma<<<dim3(16, 4, 2), 256, GEMM_SMEM>>>(bias, out, 6);
}

// round 16
// speedup vs baseline: 1.0714x; 1.0002x over previous
#include <cuda_runtime.h>
#include <cuda_bf16.h>
#include <math.h>
#include <stdint.h>

// Shapes (fixed by the problem)
#define TDIM 2048   // T == S
#define CDIM 512    // I == O == E == Ev
#define BB   2
#define NBH  16     // B*H
#define DK   64     // KEY_DIM == VALUE_DIM
#define HKT  (DK * TDIM / 2)      // uint32 (bf16x2) per bh plane

// Pre-split bf16 hi/lo packed (bf16x2 along the fast axis) device scratch.
__device__ uint32_t g_Kh[NBH * HKT], g_Kl[NBH * HKT];
__device__ uint32_t g_Vh[NBH * HKT], g_Vl[NBH * HKT];
__device__ uint32_t g_Qh[NBH * HKT], g_Ql[NBH * HKT];
__device__ uint32_t g_Oh[BB * CDIM * TDIM / 2], g_Ol[BB * CDIM * TDIM / 2];
__device__ uint32_t g_Xh[BB * CDIM * TDIM / 2], g_Xl[BB * CDIM * TDIM / 2];
__device__ uint32_t g_Yh[BB * CDIM * TDIM / 2], g_Yl[BB * CDIM * TDIM / 2];
__device__ uint32_t g_Wph[4 * CDIM * CDIM / 2], g_Wpl[4 * CDIM * CDIM / 2];

// ============================================================================
// Warp-MMA helpers (baseline PTX: works on plain sm_103 target)
// ============================================================================
__device__ __forceinline__ uint32_t smem_u32(const void* p) {
    uint32_t a;
    asm("{ .reg .u64 t; cvta.to.shared.u64 t, %1; cvt.u32.u64 %0, t; }"
        : "=r"(a) : "l"(p));
    return a;
}
__device__ __forceinline__ void ldsm_x4(uint32_t addr, uint32_t* r) {
    asm volatile("ldmatrix.sync.aligned.m8n8.x4.shared.b16 {%0,%1,%2,%3}, [%4];"
                 : "=r"(r[0]), "=r"(r[1]), "=r"(r[2]), "=r"(r[3]) : "r"(addr));
}
__device__ __forceinline__ void ldsm_x4t(uint32_t addr, uint32_t* r) {
    asm volatile("ldmatrix.sync.aligned.m8n8.x4.trans.shared.b16 {%0,%1,%2,%3}, [%4];"
                 : "=r"(r[0]), "=r"(r[1]), "=r"(r[2]), "=r"(r[3]) : "r"(addr));
}
__device__ __forceinline__ uint32_t movm(uint32_t s) {
    uint32_t d;
    asm volatile("movmatrix.sync.aligned.m8n8.trans.b16 %0, %1;"
                 : "=r"(d) : "r"(s));
    return d;
}
__device__ __forceinline__ void mma_bf16(float* d, const uint32_t* a,
                                         const uint32_t* b) {
    asm volatile(
        "mma.sync.aligned.m16n8k16.row.col.f32.bf16.bf16.f32 "
        "{%0,%1,%2,%3}, {%4,%5,%6,%7}, {%8,%9}, {%0,%1,%2,%3};"
        : "+f"(d[0]), "+f"(d[1]), "+f"(d[2]), "+f"(d[3])
        : "r"(a[0]), "r"(a[1]), "r"(a[2]), "r"(a[3]), "r"(b[0]), "r"(b[1]));
}
__device__ __forceinline__ void cpa16(uint32_t smem_dst, const void* gsrc) {
    asm volatile("cp.async.cg.shared.global [%0], [%1], 16;"
                 :: "r"(smem_dst), "l"(gsrc));
}
#define CPA_COMMIT() asm volatile("cp.async.commit_group;" ::: "memory")
#define CPA_WAIT0()  asm volatile("cp.async.wait_group 0;" ::: "memory")
#define CPA_WAIT1()  asm volatile("cp.async.wait_group 1;" ::: "memory")

__device__ __forceinline__ uint32_t pack2(float lo, float hi) {
    uint32_t r;
    asm("cvt.rn.bf16x2.f32 %0, %1, %2;" : "=r"(r) : "f"(hi), "f"(lo));
    return r;
}
__device__ __forceinline__ void split2(float a, float b, uint32_t& hi, uint32_t& lo) {
    hi = pack2(a, b);
    float ha = __int_as_float(hi << 16);
    float hb = __int_as_float(hi & 0xffff0000u);
    lo = pack2(a - ha, b - hb);
}
__device__ __forceinline__ void split4(float4 v, uint2& hi, uint2& lo) {
    split2(v.x, v.y, hi.x, lo.x);
    split2(v.z, v.w, hi.y, lo.y);
}

// MUFU-pipe exp2 (tensor cores own GEMMs; MUFU is otherwise idle)
__device__ __forceinline__ float ex2a(float x) {
    float y;
    asm("ex2.approx.f32 %0, %1;" : "=f"(y) : "f"(x));
    return y;
}
#define C_EXP8 0.18033688f   // log2(e) / 8

// ============================================================================
// Prep: split x, y, and all weights into packed bf16 hi/lo
// ============================================================================
#define PREP_THREADS (524288 * 2 + 4 * 65536)   // 1,310,720

__global__ void __launch_bounds__(256) prep_split(
    const float* __restrict__ x, const float* __restrict__ y,
    const float* __restrict__ Wk, const float* __restrict__ Wv,
    const float* __restrict__ Wq, const float* __restrict__ Wf)
{
    int idx = blockIdx.x * 256 + threadIdx.x;
    const float* src; uint32_t* dh; uint32_t* dl; size_t off, dst;
    if (idx < 524288) {
        src = x; dh = g_Xh; dl = g_Xl; off = idx; dst = (size_t)idx * 2;
    } else if (idx < 1048576) {
        int w = idx - 524288;
        src = y; dh = g_Yh; dl = g_Yl; off = w; dst = (size_t)w * 2;
    } else {
        int w = idx - 1048576;
        int pj = w >> 16, loc = w & 65535;
        src = (pj == 0) ? Wk : (pj == 1) ? Wv : (pj == 2) ? Wq : Wf;
        dh = g_Wph; dl = g_Wpl; off = loc; dst = (size_t)w * 2;
    }
    float4 v = *(const float4*)(src + off * 4);
    uint2 hi, lo; split4(v, hi, lo);
    dh[dst] = hi.x; dh[dst + 1] = hi.y;
    dl[dst] = lo.x; dl[dst + 1] = lo.y;
}

// ============================================================================
// bf16x3 HMMA GEMM (R12 config; MMA emission reordered term-major so
// same-accumulator MMAs are spaced by 8 independent ones — per-accumulator
// add order unchanged (hh, hl, lh) -> bitwise-identical results)
// ============================================================================
#define A_STR_B 144
#define B_STR_B 272
#define SA_HI 0
#define SA_LO 18432
#define SB_HI 36864
#define SB_LO 54272
#define STAGE 71680
#define GEMM_SMEM (2 * STAGE)

__device__ __forceinline__ void gemm_fill(uint32_t sbs, const uint32_t* Ah,
                                          const uint32_t* Al, const uint32_t* Bh,
                                          const uint32_t* Bl, int k0, int tid) {
    #pragma unroll
    for (int q = 0; q < 4; q++) {
        int idx = q * 256 + tid, r = idx >> 3, c = idx & 7;
        uint32_t so = (uint32_t)(r * A_STR_B + c * 16);
        size_t gi = (size_t)r * (CDIM / 2) + k0 / 2 + c * 4;
        cpa16(sbs + SA_HI + so, Ah + gi);
        cpa16(sbs + SA_LO + so, Al + gi);
    }
    #pragma unroll
    for (int q = 0; q < 4; q++) {
        int idx = q * 256 + tid, r = idx >> 4, c = idx & 15;
        uint32_t so = (uint32_t)(r * B_STR_B + c * 16);
        size_t gi = (size_t)(k0 + r) * (TDIM / 2) + c * 4;
        cpa16(sbs + SB_HI + so, Bh + gi);
        cpa16(sbs + SB_LO + so, Bl + gi);
    }
}

__global__ void __launch_bounds__(256, 1) gemm_mma(
    const float* __restrict__ bias, float* __restrict__ out, int zbase)
{
    extern __shared__ char smem[];
    uint32_t sb = smem_u32(smem);
    int tid = threadIdx.x, wid = tid >> 5, lane = tid & 31;

    int z = blockIdx.z + zbase;
    int m0 = blockIdx.y * 128, n0 = blockIdx.x * 128;
    const uint32_t *Ah, *Al, *Bh, *Bl;
    uint32_t *Ch = nullptr, *Cl = nullptr;
    float* Od = nullptr;
    size_t cbase = 0;
    if (z < 6) {
        int proj = z >> 1, b = z & 1;
        Ah = g_Wph + (size_t)proj * CDIM * (CDIM / 2);
        Al = g_Wpl + (size_t)proj * CDIM * (CDIM / 2);
        const uint32_t* Xh = (proj == 2) ? g_Yh : g_Xh;
        const uint32_t* Xl = (proj == 2) ? g_Yl : g_Xl;
        Bh = Xh + (size_t)b * CDIM * (TDIM / 2);
        Bl = Xl + (size_t)b * CDIM * (TDIM / 2);
        Ch = (proj == 0) ? g_Kh : (proj == 1) ? g_Vh : g_Qh;
        Cl = (proj == 0) ? g_Kl : (proj == 1) ? g_Vl : g_Ql;
        cbase = (size_t)b * CDIM * (TDIM / 2);
    } else {
        int b = z - 6;
        Ah = g_Wph + (size_t)3 * CDIM * (CDIM / 2);
        Al = g_Wpl + (size_t)3 * CDIM * (CDIM / 2);
        Bh = g_Oh + (size_t)b * CDIM * (TDIM / 2);
        Bl = g_Ol + (size_t)b * CDIM * (TDIM / 2);
        Od = out + (size_t)b * TDIM * CDIM;
    }
    Ah += (size_t)m0 * (CDIM / 2);
    Al += (size_t)m0 * (CDIM / 2);
    Bh += n0 / 2;
    Bl += n0 / 2;

    int wm = (wid & 1) * 64;
    int wn = (wid >> 1) * 32;

    float d[4][4][4] = {};

    gemm_fill(sb, Ah, Al, Bh, Bl, 0, tid);
    CPA_COMMIT();

    #pragma unroll 1
    for (int s = 0; s < 8; s++) {
        uint32_t sbs = sb + (uint32_t)(s & 1) * STAGE;
        if (s < 7) {
            gemm_fill(sb + (uint32_t)((s + 1) & 1) * STAGE,
                      Ah, Al, Bh, Bl, (s + 1) * 64, tid);
            CPA_COMMIT();
            CPA_WAIT1();
        } else {
            CPA_WAIT0();
        }
        __syncthreads();

        #pragma unroll
        for (int kk = 0; kk < 4; kk++) {
            uint32_t ah[4][4], al[4][4];
            #pragma unroll
            for (int mf = 0; mf < 4; mf++) {
                uint32_t addr = sbs
                    + (uint32_t)((wm + mf * 16 + (lane & 15)) * A_STR_B)
                    + (uint32_t)((kk * 16 + (lane >> 4) * 8) * 2);
                ldsm_x4(addr + SA_HI, ah[mf]);
                ldsm_x4(addr + SA_LO, al[mf]);
            }
            #pragma unroll
            for (int nf2 = 0; nf2 < 2; nf2++) {
                uint32_t baddr = sbs
                    + (uint32_t)((kk * 16 + (lane & 15)) * B_STR_B)
                    + (uint32_t)((wn + nf2 * 16 + (lane >> 4) * 8) * 2);
                uint32_t bh[4], bl[4];
                ldsm_x4t(baddr + SB_HI, bh);
                ldsm_x4t(baddr + SB_LO, bl);
                // pass 1: hi*hi  (8 independent accumulators)
                #pragma unroll
                for (int mf = 0; mf < 4; mf++)
                    #pragma unroll
                    for (int h = 0; h < 2; h++)
                        mma_bf16(d[mf][nf2 * 2 + h], ah[mf], &bh[h * 2]);
                // pass 2: hi*lo
                #pragma unroll
                for (int mf = 0; mf < 4; mf++)
                    #pragma unroll
                    for (int h = 0; h < 2; h++)
                        mma_bf16(d[mf][nf2 * 2 + h], ah[mf], &bl[h * 2]);
                // pass 3: lo*hi
                #pragma unroll
                for (int mf = 0; mf < 4; mf++)
                    #pragma unroll
                    for (int h = 0; h < 2; h++)
                        mma_bf16(d[mf][nf2 * 2 + h], al[mf], &bh[h * 2]);
            }
        }
        __syncthreads();
    }

    int g = lane >> 2, t = lane & 3;
    if (!Od) {
        #pragma unroll
        for (int mf = 0; mf < 4; mf++) {
            int e = m0 + wm + mf * 16 + g;
            #pragma unroll
            for (int nf = 0; nf < 4; nf++) {
                int npair = (n0 + wn + nf * 8) / 2 + t;
                uint32_t hp0, lp0, hp1, lp1;
                split2(d[mf][nf][0], d[mf][nf][1], hp0, lp0);
                split2(d[mf][nf][2], d[mf][nf][3], hp1, lp1);
                size_t ix = cbase + (size_t)e * (TDIM / 2) + npair;
                Ch[ix] = hp0;                  Cl[ix] = lp0;
                Ch[ix + 8 * (TDIM / 2)] = hp1; Cl[ix + 8 * (TDIM / 2)] = lp1;
            }
        }
    } else {
        float* tr = (float*)smem;
        #pragma unroll
        for (int mf = 0; mf < 4; mf++) {
            #pragma unroll
            for (int nf = 0; nf < 4; nf++) {
                int mm = wm + mf * 16 + g;
                int nn = wn + nf * 8 + t * 2;
                tr[(nn + 0) * 132 + mm]     = d[mf][nf][0];
                tr[(nn + 1) * 132 + mm]     = d[mf][nf][1];
                tr[(nn + 0) * 132 + mm + 8] = d[mf][nf][2];
                tr[(nn + 1) * 132 + mm + 8] = d[mf][nf][3];
            }
        }
        __syncthreads();
        int rr = tid >> 1, hh = (tid & 1) * 64;
        float* drow = Od + (size_t)(n0 + rr) * CDIM + m0 + hh;
        const float* bv = bias + m0 + hh;
        #pragma unroll
        for (int j = 0; j < 16; j++) {
            float4 v = *(float4*)&tr[rr * 132 + hh + j * 4];
            v.x += bv[j*4+0]; v.y += bv[j*4+1]; v.z += bv[j*4+2]; v.w += bv[j*4+3];
            *(float4*)(drow + j * 4) = v;
        }
    }
}

// ============================================================================
// HMMA flash attention (R12 config: 128 thr / 4 warps, 64-wide s-block,
// 2 CTAs/SM). MMA emission reordered term-major (same per-accumulator
// order -> bitwise identical); PV hoists V fragments per kb block.
// ============================================================================
#define STR  272
#define QSTR 144
#define SM_QH 0
#define SM_QL 9216
#define SM_KH 18432
#define SM_KL 35840
#define SM_VH 53248
#define SM_VL 70656
#define SM_L  88064
#define SM_RED 88320
#define ATTN_SMEM 88832

__global__ void __launch_bounds__(128) attn_mma(const float* __restrict__ mask)
{
    extern __shared__ char smem[];
    uint32_t sb = smem_u32(smem);
    float* l_sm = (float*)(smem + SM_L);
    float* red  = (float*)(smem + SM_RED);

    int tid = threadIdx.x, wid = tid >> 5, lane = tid & 31;
    int g = lane >> 2, t2 = lane & 3;
    int bh = blockIdx.y, s0 = blockIdx.x * 64;
    int wt  = (wid & 1) * 64;      // t-half
    int wss = (wid >> 1) * 32;     // s-group (2 groups x 32s)

    const uint32_t* Kh = g_Kh + (size_t)bh * HKT;
    const uint32_t* Kl = g_Kl + (size_t)bh * HKT;
    const uint32_t* Vh = g_Vh + (size_t)bh * HKT;
    const uint32_t* Vl = g_Vl + (size_t)bh * HKT;
    const uint32_t* Qh = g_Qh + (size_t)bh * HKT;
    const uint32_t* Ql = g_Ql + (size_t)bh * HKT;

    // ---- preamble: Q (64k x 64s) + K(0) in one group
    #pragma unroll
    for (int q = 0; q < 4; q++) {
        int idx = q * 128 + tid, r = idx >> 3, c = idx & 7;
        uint32_t so = (uint32_t)(r * QSTR + c * 16);
        const size_t qix = (size_t)r * (TDIM / 2) + s0 / 2 + c * 4;
        cpa16(sb + SM_QH + so, Qh + qix);
        cpa16(sb + SM_QL + so, Ql + qix);
    }
    #pragma unroll
    for (int q = 0; q < 8; q++) {
        int idx = q * 128 + tid, r = idx >> 4, c16 = idx & 15;
        uint32_t so = (uint32_t)(r * STR + c16 * 16);
        const size_t kix = (size_t)r * (TDIM / 2) + c16 * 4;
        cpa16(sb + SM_KH + so, Kh + kix);
        cpa16(sb + SM_KL + so, Kl + kix);
    }
    CPA_COMMIT();

    float o[4][4][4] = {};        // partial O: [vf(16v)][nf(8s)][frags]
    float lacc[8];
    #pragma unroll
    for (int j = 0; j < 8; j++) lacc[j] = 0.0f;

    #pragma unroll 1
    for (int t0 = 0; t0 < TDIM; t0 += 128) {
        int tpn = ((t0 + 128) & (TDIM - 1)) / 2;

        CPA_WAIT0();       // K(t) landed
        __syncthreads();   // prev PV done reading V; K visible

        // issue V(t)
        #pragma unroll
        for (int q = 0; q < 8; q++) {
            int idx = q * 128 + tid, r = idx >> 4, c16 = idx & 15;
            uint32_t so = (uint32_t)(r * STR + c16 * 16);
            const size_t gix = (size_t)r * (TDIM / 2) + t0 / 2 + c16 * 4;
            cpa16(sb + SM_VH + so, Vh + gix);
            cpa16(sb + SM_VL + so, Vl + gix);
        }
        CPA_COMMIT();

        // ---- scores: S[t][s] = K^T Q over warp tile 64t x 32s
        float sc[4][4][4] = {};
        #pragma unroll
        for (int kk = 0; kk < 4; kk++) {
            uint32_t ah[4][4], al[4][4];
            #pragma unroll
            for (int mf = 0; mf < 4; mf++) {
                uint32_t ar = sb
                    + (uint32_t)((kk * 16 + (lane & 7) + ((lane >> 4) << 3)) * STR)
                    + (uint32_t)((wt + mf * 16 + (((lane >> 3) & 1) << 3)) * 2);
                ldsm_x4t(ar + SM_KH, ah[mf]);
                ldsm_x4t(ar + SM_KL, al[mf]);
            }
            #pragma unroll
            for (int nf2 = 0; nf2 < 2; nf2++) {
                uint32_t br = sb
                    + (uint32_t)((kk * 16 + (lane & 15)) * QSTR)
                    + (uint32_t)((wss + nf2 * 16 + ((lane >> 4) << 3)) * 2);
                uint32_t bh4[4], bl4[4];
                ldsm_x4t(br + SM_QH, bh4);
                ldsm_x4t(br + SM_QL, bl4);
                // pass 1: hi*hi
                #pragma unroll
                for (int mf = 0; mf < 4; mf++)
                    #pragma unroll
                    for (int h = 0; h < 2; h++)
                        mma_bf16(sc[mf][nf2 * 2 + h], ah[mf], &bh4[h * 2]);
                // pass 2: hi*lo
                #pragma unroll
                for (int mf = 0; mf < 4; mf++)
                    #pragma unroll
                    for (int h = 0; h < 2; h++)
                        mma_bf16(sc[mf][nf2 * 2 + h], ah[mf], &bl4[h * 2]);
                // pass 3: lo*hi
                #pragma unroll
                for (int mf = 0; mf < 4; mf++)
                    #pragma unroll
                    for (int h = 0; h < 2; h++)
                        mma_bf16(sc[mf][nf2 * 2 + h], al[mf], &bh4[h * 2]);
            }
        }

        // ---- mask (direct LDG) + exp2 on MUFU, l in regs
        #pragma unroll
        for (int mf = 0; mf < 4; mf++) {
            #pragma unroll
            for (int j2 = 0; j2 < 2; j2++) {
                int tl = wt + mf * 16 + g + j2 * 8;
                const float* mrow = mask + (size_t)(t0 + tl) * TDIM + s0 + wss;
                #pragma unroll
                for (int nf = 0; nf < 4; nf++) {
                    float2 mk = *(const float2*)(mrow + nf * 8 + t2 * 2);
                    float e0 = ex2a((sc[mf][nf][j2 * 2 + 0] + mk.x) * C_EXP8);
                    float e1 = ex2a((sc[mf][nf][j2 * 2 + 1] + mk.y) * C_EXP8);
                    sc[mf][nf][j2 * 2 + 0] = e0;
                    sc[mf][nf][j2 * 2 + 1] = e1;
                    lacc[nf * 2 + 0] += e0;
                    lacc[nf * 2 + 1] += e1;
                }
            }
        }
        __syncthreads();   // all warps done reading K(t)

        // issue K(t+1) — stays in flight through PV
        #pragma unroll
        for (int q = 0; q < 8; q++) {
            int idx = q * 128 + tid, r = idx >> 4, c16 = idx & 15;
            uint32_t so = (uint32_t)(r * STR + c16 * 16);
            const size_t gix = (size_t)r * (TDIM / 2) + tpn + c16 * 4;
            cpa16(sb + SM_KH + so, Kh + gix);
            cpa16(sb + SM_KL + so, Kl + gix);
        }
        CPA_COMMIT();
        CPA_WAIT1();       // drain V(t); keep K(t+1) in flight
        __syncthreads();   // V(t) visible

        // ---- PV: O[v][s] += V[v][t] * P[t][s]; P from registers via movmatrix
        #pragma unroll
        for (int kb = 0; kb < 4; kb++) {
            uint32_t Bh[8], Bl[8];
            #pragma unroll
            for (int nf = 0; nf < 4; nf++) {
                uint32_t h0, l0, h1, l1;
                split2(sc[kb][nf][0], sc[kb][nf][1], h0, l0);
                split2(sc[kb][nf][2], sc[kb][nf][3], h1, l1);
                Bh[nf * 2 + 0] = movm(h0);  Bh[nf * 2 + 1] = movm(h1);
                Bl[nf * 2 + 0] = movm(l0);  Bl[nf * 2 + 1] = movm(l1);
            }
            // hoist all V fragments for this kb block
            uint32_t avh[4][4], avl[4][4];
            #pragma unroll
            for (int vf = 0; vf < 4; vf++) {
                uint32_t ar = sb
                    + (uint32_t)((vf * 16 + (lane & 15)) * STR)
                    + (uint32_t)((wt + kb * 16 + ((lane >> 4) << 3)) * 2);
                ldsm_x4(ar + SM_VH, avh[vf]);
                ldsm_x4(ar + SM_VL, avl[vf]);
            }
            // pass 1: hi*hi  (16 independent accumulators)
            #pragma unroll
            for (int vf = 0; vf < 4; vf++)
                #pragma unroll
                for (int nf = 0; nf < 4; nf++)
                    mma_bf16(o[vf][nf], avh[vf], &Bh[nf * 2]);
            // pass 2: hi*lo
            #pragma unroll
            for (int vf = 0; vf < 4; vf++)
                #pragma unroll
                for (int nf = 0; nf < 4; nf++)
                    mma_bf16(o[vf][nf], avh[vf], &Bl[nf * 2]);
            // pass 3: lo*hi
            #pragma unroll
            for (int vf = 0; vf < 4; vf++)
                #pragma unroll
                for (int nf = 0; nf < 4; nf++)
                    mma_bf16(o[vf][nf], avl[vf], &Bh[nf * 2]);
        }
    }

    // ---- epilogue
    CPA_WAIT0();           // drain trailing K prefetch before reusing smem
    __syncthreads();

    #pragma unroll
    for (int j = 0; j < 8; j++) {
        lacc[j] += __shfl_xor_sync(0xffffffffu, lacc[j], 4);
        lacc[j] += __shfl_xor_sync(0xffffffffu, lacc[j], 8);
        lacc[j] += __shfl_xor_sync(0xffffffffu, lacc[j], 16);
    }
    if (g == 0) {
        #pragma unroll
        for (int nf = 0; nf < 4; nf++) {
            red[(wid & 1) * 64 + wss + nf * 8 + t2 * 2 + 0] = lacc[nf * 2 + 0];
            red[(wid & 1) * 64 + wss + nf * 8 + t2 * 2 + 1] = lacc[nf * 2 + 1];
        }
    }
    // store O partials per warp: [v(64)][s_local(32)] fp32 (32 KB total)
    float* part = (float*)smem;
    {
        float* pw = part + wid * 2048;
        #pragma unroll
        for (int vf = 0; vf < 4; vf++) {
            #pragma unroll
            for (int nf = 0; nf < 4; nf++) {
                int v = vf * 16 + g, sl = nf * 8 + t2 * 2;
                pw[(v + 0) * 32 + sl]     = o[vf][nf][0];
                pw[(v + 0) * 32 + sl + 1] = o[vf][nf][1];
                pw[(v + 8) * 32 + sl]     = o[vf][nf][2];
                pw[(v + 8) * 32 + sl + 1] = o[vf][nf][3];
            }
        }
    }
    __syncthreads();
    if (tid < 64) l_sm[tid] = red[tid] + red[64 + tid];
    __syncthreads();

    // final: sum 2 t-half partials, normalize, pack, store
    uint32_t* Ohp = g_Oh + (size_t)bh * DK * (TDIM / 2);
    uint32_t* Olp = g_Ol + (size_t)bh * DK * (TDIM / 2);
    int v = tid >> 1;
    #pragma unroll
    for (int j = 0; j < 16; j++) {
        int sp = (tid & 1) * 16 + j;          // s pair index 0..31
        int s  = sp * 2;
        int sg = s >> 5;                       // s-group (0/1)
        const float* r0 = part + (sg * 2 + 0) * 2048 + v * 32;
        const float* r1 = part + (sg * 2 + 1) * 2048 + v * 32;
        int sl = s & 31;
        float f0 = (r0[sl]     + r1[sl])     / l_sm[s];
        float f1 = (r0[sl + 1] + r1[sl + 1]) / l_sm[s + 1];
        uint32_t hp, lp; split2(f0, f1, hp, lp);
        size_t ix = (size_t)v * (TDIM / 2) + s0 / 2 + sp;
        Ohp[ix] = hp; Olp[ix] = lp;
    }
}

// ---------------------------------------------------------------------------
extern "C" void kernel_launch(void* const* d_in, const int* in_sizes, int n_in,
                              void* d_out, int out_size)
{
    const float* x    = (const float*)d_in[0];
    const float* y    = (const float*)d_in[1];
    const float* mask = (const float*)d_in[2];
    const float* Wk   = (const float*)d_in[3];
    const float* Wv   = (const float*)d_in[4];
    const float* Wq   = (const float*)d_in[5];
    const float* W    = (const float*)d_in[6];
    const float* bias = (const float*)d_in[7];
    float* out = (float*)d_out;

    cudaFuncSetAttribute(gemm_mma, cudaFuncAttributeMaxDynamicSharedMemorySize,
                         GEMM_SMEM);
    cudaFuncSetAttribute(attn_mma, cudaFuncAttributeMaxDynamicSharedMemorySize,
                         ATTN_SMEM);

    // 0) split all fp32 inputs into packed bf16 hi/lo
    prep_split<<<PREP_THREADS / 256, 256>>>(x, y, Wk, Wv, Wq, W);
    // 1) K,V,Q projections — R12 config + term-major MMA order
    gemm_mma<<<dim3(16, 4, 6), 256, GEMM_SMEM>>>(bias, out, 0);
    // 2) HMMA flash attention — R12 config + term-major MMA order
    attn_mma<<<dim3(32, NBH), 128, ATTN_SMEM>>>(mask);
    // 3) output projection + bias
    gemm_mma<<<dim3(16, 4, 2), 256, GEMM_SMEM>>>(bias, out, 6);
}

// round 17
// speedup vs baseline: 1.0868x; 1.0144x over previous
#include <cuda_runtime.h>
#include <cuda_bf16.h>
#include <math.h>
#include <stdint.h>

// Shapes (fixed by the problem)
#define TDIM 2048   // T == S
#define CDIM 512    // I == O == E == Ev
#define BB   2
#define NBH  16     // B*H
#define DK   64     // KEY_DIM == VALUE_DIM
#define HKT  (DK * TDIM / 2)      // uint32 (bf16x2) per bh plane

// Pre-split bf16 hi/lo packed (bf16x2 along the fast axis) device scratch.
__device__ uint32_t g_Kh[NBH * HKT], g_Kl[NBH * HKT];
__device__ uint32_t g_Vh[NBH * HKT], g_Vl[NBH * HKT];
__device__ uint32_t g_Qh[NBH * HKT], g_Ql[NBH * HKT];
__device__ uint32_t g_Oh[BB * CDIM * TDIM / 2], g_Ol[BB * CDIM * TDIM / 2];
__device__ uint32_t g_Xh[BB * CDIM * TDIM / 2], g_Xl[BB * CDIM * TDIM / 2];
__device__ uint32_t g_Yh[BB * CDIM * TDIM / 2], g_Yl[BB * CDIM * TDIM / 2];
__device__ uint32_t g_Wph[4 * CDIM * CDIM / 2], g_Wpl[4 * CDIM * CDIM / 2];

// ============================================================================
// Warp-MMA helpers (baseline PTX: works on plain sm_103 target)
// ============================================================================
__device__ __forceinline__ uint32_t smem_u32(const void* p) {
    uint32_t a;
    asm("{ .reg .u64 t; cvta.to.shared.u64 t, %1; cvt.u32.u64 %0, t; }"
        : "=r"(a) : "l"(p));
    return a;
}
__device__ __forceinline__ void ldsm_x4(uint32_t addr, uint32_t* r) {
    asm volatile("ldmatrix.sync.aligned.m8n8.x4.shared.b16 {%0,%1,%2,%3}, [%4];"
                 : "=r"(r[0]), "=r"(r[1]), "=r"(r[2]), "=r"(r[3]) : "r"(addr));
}
__device__ __forceinline__ void ldsm_x4t(uint32_t addr, uint32_t* r) {
    asm volatile("ldmatrix.sync.aligned.m8n8.x4.trans.shared.b16 {%0,%1,%2,%3}, [%4];"
                 : "=r"(r[0]), "=r"(r[1]), "=r"(r[2]), "=r"(r[3]) : "r"(addr));
}
__device__ __forceinline__ uint32_t movm(uint32_t s) {
    uint32_t d;
    asm volatile("movmatrix.sync.aligned.m8n8.trans.b16 %0, %1;"
                 : "=r"(d) : "r"(s));
    return d;
}
__device__ __forceinline__ void mma_bf16(float* d, const uint32_t* a,
                                         const uint32_t* b) {
    asm volatile(
        "mma.sync.aligned.m16n8k16.row.col.f32.bf16.bf16.f32 "
        "{%0,%1,%2,%3}, {%4,%5,%6,%7}, {%8,%9}, {%0,%1,%2,%3};"
        : "+f"(d[0]), "+f"(d[1]), "+f"(d[2]), "+f"(d[3])
        : "r"(a[0]), "r"(a[1]), "r"(a[2]), "r"(a[3]), "r"(b[0]), "r"(b[1]));
}
__device__ __forceinline__ void cpa16(uint32_t smem_dst, const void* gsrc) {
    asm volatile("cp.async.cg.shared.global [%0], [%1], 16;"
                 :: "r"(smem_dst), "l"(gsrc));
}
#define CPA_COMMIT() asm volatile("cp.async.commit_group;" ::: "memory")
#define CPA_WAIT0()  asm volatile("cp.async.wait_group 0;" ::: "memory")
#define CPA_WAIT1()  asm volatile("cp.async.wait_group 1;" ::: "memory")

__device__ __forceinline__ uint32_t pack2(float lo, float hi) {
    uint32_t r;
    asm("cvt.rn.bf16x2.f32 %0, %1, %2;" : "=r"(r) : "f"(hi), "f"(lo));
    return r;
}
__device__ __forceinline__ void split2(float a, float b, uint32_t& hi, uint32_t& lo) {
    hi = pack2(a, b);
    float ha = __int_as_float(hi << 16);
    float hb = __int_as_float(hi & 0xffff0000u);
    lo = pack2(a - ha, b - hb);
}
__device__ __forceinline__ void split4(float4 v, uint2& hi, uint2& lo) {
    split2(v.x, v.y, hi.x, lo.x);
    split2(v.z, v.w, hi.y, lo.y);
}

// MUFU-pipe exp2 (tensor cores own GEMMs; MUFU is otherwise idle)
__device__ __forceinline__ float ex2a(float x) {
    float y;
    asm("ex2.approx.f32 %0, %1;" : "=f"(y) : "f"(x));
    return y;
}
#define C_EXP8 0.18033688f   // log2(e) / 8

// ============================================================================
// Prep: split x, y, and all weights into packed bf16 hi/lo
// ============================================================================
#define PREP_THREADS (524288 * 2 + 4 * 65536)   // 1,310,720

__global__ void __launch_bounds__(256) prep_split(
    const float* __restrict__ x, const float* __restrict__ y,
    const float* __restrict__ Wk, const float* __restrict__ Wv,
    const float* __restrict__ Wq, const float* __restrict__ Wf)
{
    int idx = blockIdx.x * 256 + threadIdx.x;
    const float* src; uint32_t* dh; uint32_t* dl; size_t off, dst;
    if (idx < 524288) {
        src = x; dh = g_Xh; dl = g_Xl; off = idx; dst = (size_t)idx * 2;
    } else if (idx < 1048576) {
        int w = idx - 524288;
        src = y; dh = g_Yh; dl = g_Yl; off = w; dst = (size_t)w * 2;
    } else {
        int w = idx - 1048576;
        int pj = w >> 16, loc = w & 65535;
        src = (pj == 0) ? Wk : (pj == 1) ? Wv : (pj == 2) ? Wq : Wf;
        dh = g_Wph; dl = g_Wpl; off = loc; dst = (size_t)w * 2;
    }
    float4 v = *(const float4*)(src + off * 4);
    uint2 hi, lo; split4(v, hi, lo);
    dh[dst] = hi.x; dh[dst + 1] = hi.y;
    dl[dst] = lo.x; dl[dst + 1] = lo.y;
}

// ============================================================================
// bf16x3 HMMA GEMM (R12 measured-best config, term-major emission)
// ============================================================================
#define A_STR_B 144
#define B_STR_B 272
#define SA_HI 0
#define SA_LO 18432
#define SB_HI 36864
#define SB_LO 54272
#define STAGE 71680
#define GEMM_SMEM (2 * STAGE)

__device__ __forceinline__ void gemm_fill(uint32_t sbs, const uint32_t* Ah,
                                          const uint32_t* Al, const uint32_t* Bh,
                                          const uint32_t* Bl, int k0, int tid) {
    #pragma unroll
    for (int q = 0; q < 4; q++) {
        int idx = q * 256 + tid, r = idx >> 3, c = idx & 7;
        uint32_t so = (uint32_t)(r * A_STR_B + c * 16);
        size_t gi = (size_t)r * (CDIM / 2) + k0 / 2 + c * 4;
        cpa16(sbs + SA_HI + so, Ah + gi);
        cpa16(sbs + SA_LO + so, Al + gi);
    }
    #pragma unroll
    for (int q = 0; q < 4; q++) {
        int idx = q * 256 + tid, r = idx >> 4, c = idx & 15;
        uint32_t so = (uint32_t)(r * B_STR_B + c * 16);
        size_t gi = (size_t)(k0 + r) * (TDIM / 2) + c * 4;
        cpa16(sbs + SB_HI + so, Bh + gi);
        cpa16(sbs + SB_LO + so, Bl + gi);
    }
}

__global__ void __launch_bounds__(256, 1) gemm_mma(
    const float* __restrict__ bias, float* __restrict__ out, int zbase)
{
    extern __shared__ char smem[];
    uint32_t sb = smem_u32(smem);
    int tid = threadIdx.x, wid = tid >> 5, lane = tid & 31;

    int z = blockIdx.z + zbase;
    int m0 = blockIdx.y * 128, n0 = blockIdx.x * 128;
    const uint32_t *Ah, *Al, *Bh, *Bl;
    uint32_t *Ch = nullptr, *Cl = nullptr;
    float* Od = nullptr;
    size_t cbase = 0;
    if (z < 6) {
        int proj = z >> 1, b = z & 1;
        Ah = g_Wph + (size_t)proj * CDIM * (CDIM / 2);
        Al = g_Wpl + (size_t)proj * CDIM * (CDIM / 2);
        const uint32_t* Xh = (proj == 2) ? g_Yh : g_Xh;
        const uint32_t* Xl = (proj == 2) ? g_Yl : g_Xl;
        Bh = Xh + (size_t)b * CDIM * (TDIM / 2);
        Bl = Xl + (size_t)b * CDIM * (TDIM / 2);
        Ch = (proj == 0) ? g_Kh : (proj == 1) ? g_Vh : g_Qh;
        Cl = (proj == 0) ? g_Kl : (proj == 1) ? g_Vl : g_Ql;
        cbase = (size_t)b * CDIM * (TDIM / 2);
    } else {
        int b = z - 6;
        Ah = g_Wph + (size_t)3 * CDIM * (CDIM / 2);
        Al = g_Wpl + (size_t)3 * CDIM * (CDIM / 2);
        Bh = g_Oh + (size_t)b * CDIM * (TDIM / 2);
        Bl = g_Ol + (size_t)b * CDIM * (TDIM / 2);
        Od = out + (size_t)b * TDIM * CDIM;
    }
    Ah += (size_t)m0 * (CDIM / 2);
    Al += (size_t)m0 * (CDIM / 2);
    Bh += n0 / 2;
    Bl += n0 / 2;

    int wm = (wid & 1) * 64;
    int wn = (wid >> 1) * 32;

    float d[4][4][4] = {};

    gemm_fill(sb, Ah, Al, Bh, Bl, 0, tid);
    CPA_COMMIT();

    #pragma unroll 1
    for (int s = 0; s < 8; s++) {
        uint32_t sbs = sb + (uint32_t)(s & 1) * STAGE;
        if (s < 7) {
            gemm_fill(sb + (uint32_t)((s + 1) & 1) * STAGE,
                      Ah, Al, Bh, Bl, (s + 1) * 64, tid);
            CPA_COMMIT();
            CPA_WAIT1();
        } else {
            CPA_WAIT0();
        }
        __syncthreads();

        #pragma unroll
        for (int kk = 0; kk < 4; kk++) {
            uint32_t ah[4][4], al[4][4];
            #pragma unroll
            for (int mf = 0; mf < 4; mf++) {
                uint32_t addr = sbs
                    + (uint32_t)((wm + mf * 16 + (lane & 15)) * A_STR_B)
                    + (uint32_t)((kk * 16 + (lane >> 4) * 8) * 2);
                ldsm_x4(addr + SA_HI, ah[mf]);
                ldsm_x4(addr + SA_LO, al[mf]);
            }
            #pragma unroll
            for (int nf2 = 0; nf2 < 2; nf2++) {
                uint32_t baddr = sbs
                    + (uint32_t)((kk * 16 + (lane & 15)) * B_STR_B)
                    + (uint32_t)((wn + nf2 * 16 + (lane >> 4) * 8) * 2);
                uint32_t bh[4], bl[4];
                ldsm_x4t(baddr + SB_HI, bh);
                ldsm_x4t(baddr + SB_LO, bl);
                #pragma unroll
                for (int mf = 0; mf < 4; mf++)
                    #pragma unroll
                    for (int h = 0; h < 2; h++)
                        mma_bf16(d[mf][nf2 * 2 + h], ah[mf], &bh[h * 2]);
                #pragma unroll
                for (int mf = 0; mf < 4; mf++)
                    #pragma unroll
                    for (int h = 0; h < 2; h++)
                        mma_bf16(d[mf][nf2 * 2 + h], ah[mf], &bl[h * 2]);
                #pragma unroll
                for (int mf = 0; mf < 4; mf++)
                    #pragma unroll
                    for (int h = 0; h < 2; h++)
                        mma_bf16(d[mf][nf2 * 2 + h], al[mf], &bh[h * 2]);
            }
        }
        __syncthreads();
    }

    int g = lane >> 2, t = lane & 3;
    if (!Od) {
        #pragma unroll
        for (int mf = 0; mf < 4; mf++) {
            int e = m0 + wm + mf * 16 + g;
            #pragma unroll
            for (int nf = 0; nf < 4; nf++) {
                int npair = (n0 + wn + nf * 8) / 2 + t;
                uint32_t hp0, lp0, hp1, lp1;
                split2(d[mf][nf][0], d[mf][nf][1], hp0, lp0);
                split2(d[mf][nf][2], d[mf][nf][3], hp1, lp1);
                size_t ix = cbase + (size_t)e * (TDIM / 2) + npair;
                Ch[ix] = hp0;                  Cl[ix] = lp0;
                Ch[ix + 8 * (TDIM / 2)] = hp1; Cl[ix + 8 * (TDIM / 2)] = lp1;
            }
        }
    } else {
        float* tr = (float*)smem;
        #pragma unroll
        for (int mf = 0; mf < 4; mf++) {
            #pragma unroll
            for (int nf = 0; nf < 4; nf++) {
                int mm = wm + mf * 16 + g;
                int nn = wn + nf * 8 + t * 2;
                tr[(nn + 0) * 132 + mm]     = d[mf][nf][0];
                tr[(nn + 1) * 132 + mm]     = d[mf][nf][1];
                tr[(nn + 0) * 132 + mm + 8] = d[mf][nf][2];
                tr[(nn + 1) * 132 + mm + 8] = d[mf][nf][3];
            }
        }
        __syncthreads();
        int rr = tid >> 1, hh = (tid & 1) * 64;
        float* drow = Od + (size_t)(n0 + rr) * CDIM + m0 + hh;
        const float* bv = bias + m0 + hh;
        #pragma unroll
        for (int j = 0; j < 16; j++) {
            float4 v = *(float4*)&tr[rr * 132 + hh + j * 4];
            v.x += bv[j*4+0]; v.y += bv[j*4+1]; v.z += bv[j*4+2]; v.w += bv[j*4+3];
            *(float4*)(drow + j * 4) = v;
        }
    }
}

// ============================================================================
// HMMA flash attention, t-tile 64 (was 128): smem 55 KB -> 3 CTAs/SM if
// regs allow. 128 thr / 4 warps; warps: (wid&1)=t-half(32t), (wid>>1)=
// s-group(32s). Same verified microtile formulas with STR=144, mf<2, kb<2.
// Pipeline per tile: WAIT0(K)->sync->issue V->scores->exp->sync->
// issue K(t+1)->WAIT1(V)->sync->PV.  32 tiles of 64t.
// ============================================================================
#define STR  144                 // K/V row stride (64 t-cols x 2B + 16 pad)
#define QSTR 144
#define SM_QH 0
#define SM_QL 9216
#define SM_KH 18432
#define SM_KL 27648
#define SM_VH 36864
#define SM_VL 46080
#define SM_L  55296
#define SM_RED 55552
#define ATTN_SMEM 56320

__global__ void __launch_bounds__(128) attn_mma(const float* __restrict__ mask)
{
    extern __shared__ char smem[];
    uint32_t sb = smem_u32(smem);
    float* l_sm = (float*)(smem + SM_L);
    float* red  = (float*)(smem + SM_RED);

    int tid = threadIdx.x, wid = tid >> 5, lane = tid & 31;
    int g = lane >> 2, t2 = lane & 3;
    int bh = blockIdx.y, s0 = blockIdx.x * 64;
    int wt  = (wid & 1) * 32;      // t-half (32t of the 64t tile)
    int wss = (wid >> 1) * 32;     // s-group (2 groups x 32s)

    const uint32_t* Kh = g_Kh + (size_t)bh * HKT;
    const uint32_t* Kl = g_Kl + (size_t)bh * HKT;
    const uint32_t* Vh = g_Vh + (size_t)bh * HKT;
    const uint32_t* Vl = g_Vl + (size_t)bh * HKT;
    const uint32_t* Qh = g_Qh + (size_t)bh * HKT;
    const uint32_t* Ql = g_Ql + (size_t)bh * HKT;

    // ---- preamble: Q (64k x 64s) + K(0) (64k x 64t) in one group
    #pragma unroll
    for (int q = 0; q < 4; q++) {
        int idx = q * 128 + tid, r = idx >> 3, c = idx & 7;
        uint32_t so = (uint32_t)(r * QSTR + c * 16);
        const size_t qix = (size_t)r * (TDIM / 2) + s0 / 2 + c * 4;
        cpa16(sb + SM_QH + so, Qh + qix);
        cpa16(sb + SM_QL + so, Ql + qix);
        const size_t kix = (size_t)r * (TDIM / 2) + c * 4;   // t0 = 0
        cpa16(sb + SM_KH + so, Kh + kix);
        cpa16(sb + SM_KL + so, Kl + kix);
    }
    CPA_COMMIT();

    float o[4][4][4] = {};        // partial O: [vf(16v)][nf(8s)][frags]
    float lacc[8];
    #pragma unroll
    for (int j = 0; j < 8; j++) lacc[j] = 0.0f;

    #pragma unroll 1
    for (int t0 = 0; t0 < TDIM; t0 += 64) {
        int tpn = ((t0 + 64) & (TDIM - 1)) / 2;

        CPA_WAIT0();       // K(t) landed
        __syncthreads();   // prev PV done reading V; K visible

        // issue V(t): 64 dk rows x 64 t cols
        #pragma unroll
        for (int q = 0; q < 4; q++) {
            int idx = q * 128 + tid, r = idx >> 3, c = idx & 7;
            uint32_t so = (uint32_t)(r * STR + c * 16);
            const size_t gix = (size_t)r * (TDIM / 2) + t0 / 2 + c * 4;
            cpa16(sb + SM_VH + so, Vh + gix);
            cpa16(sb + SM_VL + so, Vl + gix);
        }
        CPA_COMMIT();

        // ---- scores: S[t][s] = K^T Q over warp tile 32t x 32s
        float sc[2][4][4] = {};
        #pragma unroll
        for (int kk = 0; kk < 4; kk++) {
            uint32_t ah[2][4], al[2][4];
            #pragma unroll
            for (int mf = 0; mf < 2; mf++) {
                uint32_t ar = sb
                    + (uint32_t)((kk * 16 + (lane & 7) + ((lane >> 4) << 3)) * STR)
                    + (uint32_t)((wt + mf * 16 + (((lane >> 3) & 1) << 3)) * 2);
                ldsm_x4t(ar + SM_KH, ah[mf]);
                ldsm_x4t(ar + SM_KL, al[mf]);
            }
            #pragma unroll
            for (int nf2 = 0; nf2 < 2; nf2++) {
                uint32_t br = sb
                    + (uint32_t)((kk * 16 + (lane & 15)) * QSTR)
                    + (uint32_t)((wss + nf2 * 16 + ((lane >> 4) << 3)) * 2);
                uint32_t bh4[4], bl4[4];
                ldsm_x4t(br + SM_QH, bh4);
                ldsm_x4t(br + SM_QL, bl4);
                #pragma unroll
                for (int mf = 0; mf < 2; mf++)
                    #pragma unroll
                    for (int h = 0; h < 2; h++)
                        mma_bf16(sc[mf][nf2 * 2 + h], ah[mf], &bh4[h * 2]);
                #pragma unroll
                for (int mf = 0; mf < 2; mf++)
                    #pragma unroll
                    for (int h = 0; h < 2; h++)
                        mma_bf16(sc[mf][nf2 * 2 + h], ah[mf], &bl4[h * 2]);
                #pragma unroll
                for (int mf = 0; mf < 2; mf++)
                    #pragma unroll
                    for (int h = 0; h < 2; h++)
                        mma_bf16(sc[mf][nf2 * 2 + h], al[mf], &bh4[h * 2]);
            }
        }

        // ---- mask (direct LDG) + exp2 on MUFU, l in regs
        #pragma unroll
        for (int mf = 0; mf < 2; mf++) {
            #pragma unroll
            for (int j2 = 0; j2 < 2; j2++) {
                int tl = wt + mf * 16 + g + j2 * 8;
                const float* mrow = mask + (size_t)(t0 + tl) * TDIM + s0 + wss;
                #pragma unroll
                for (int nf = 0; nf < 4; nf++) {
                    float2 mk = *(const float2*)(mrow + nf * 8 + t2 * 2);
                    float e0 = ex2a((sc[mf][nf][j2 * 2 + 0] + mk.x) * C_EXP8);
                    float e1 = ex2a((sc[mf][nf][j2 * 2 + 1] + mk.y) * C_EXP8);
                    sc[mf][nf][j2 * 2 + 0] = e0;
                    sc[mf][nf][j2 * 2 + 1] = e1;
                    lacc[nf * 2 + 0] += e0;
                    lacc[nf * 2 + 1] += e1;
                }
            }
        }
        __syncthreads();   // all warps done reading K(t)

        // issue K(t+1) — stays in flight through PV
        #pragma unroll
        for (int q = 0; q < 4; q++) {
            int idx = q * 128 + tid, r = idx >> 3, c = idx & 7;
            uint32_t so = (uint32_t)(r * STR + c * 16);
            const size_t gix = (size_t)r * (TDIM / 2) + tpn + c * 4;
            cpa16(sb + SM_KH + so, Kh + gix);
            cpa16(sb + SM_KL + so, Kl + gix);
        }
        CPA_COMMIT();
        CPA_WAIT1();       // drain V(t); keep K(t+1) in flight
        __syncthreads();   // V(t) visible

        // ---- PV: O[v][s] += V[v][t] * P[t][s]; P from registers via movmatrix
        #pragma unroll
        for (int kb = 0; kb < 2; kb++) {
            uint32_t Bh[8], Bl[8];
            #pragma unroll
            for (int nf = 0; nf < 4; nf++) {
                uint32_t h0, l0, h1, l1;
                split2(sc[kb][nf][0], sc[kb][nf][1], h0, l0);
                split2(sc[kb][nf][2], sc[kb][nf][3], h1, l1);
                Bh[nf * 2 + 0] = movm(h0);  Bh[nf * 2 + 1] = movm(h1);
                Bl[nf * 2 + 0] = movm(l0);  Bl[nf * 2 + 1] = movm(l1);
            }
            uint32_t avh[4][4], avl[4][4];
            #pragma unroll
            for (int vf = 0; vf < 4; vf++) {
                uint32_t ar = sb
                    + (uint32_t)((vf * 16 + (lane & 15)) * STR)
                    + (uint32_t)((wt + kb * 16 + ((lane >> 4) << 3)) * 2);
                ldsm_x4(ar + SM_VH, avh[vf]);
                ldsm_x4(ar + SM_VL, avl[vf]);
            }
            #pragma unroll
            for (int vf = 0; vf < 4; vf++)
                #pragma unroll
                for (int nf = 0; nf < 4; nf++)
                    mma_bf16(o[vf][nf], avh[vf], &Bh[nf * 2]);
            #pragma unroll
            for (int vf = 0; vf < 4; vf++)
                #pragma unroll
                for (int nf = 0; nf < 4; nf++)
                    mma_bf16(o[vf][nf], avh[vf], &Bl[nf * 2]);
            #pragma unroll
            for (int vf = 0; vf < 4; vf++)
                #pragma unroll
                for (int nf = 0; nf < 4; nf++)
                    mma_bf16(o[vf][nf], avl[vf], &Bh[nf * 2]);
        }
    }

    // ---- epilogue
    CPA_WAIT0();           // drain trailing K prefetch before reusing smem
    __syncthreads();

    #pragma unroll
    for (int j = 0; j < 8; j++) {
        lacc[j] += __shfl_xor_sync(0xffffffffu, lacc[j], 4);
        lacc[j] += __shfl_xor_sync(0xffffffffu, lacc[j], 8);
        lacc[j] += __shfl_xor_sync(0xffffffffu, lacc[j], 16);
    }
    if (g == 0) {
        #pragma unroll
        for (int nf = 0; nf < 4; nf++) {
            red[(wid & 1) * 64 + wss + nf * 8 + t2 * 2 + 0] = lacc[nf * 2 + 0];
            red[(wid & 1) * 64 + wss + nf * 8 + t2 * 2 + 1] = lacc[nf * 2 + 1];
        }
    }
    // store O partials per warp: [v(64)][s_local(32)] fp32 (32 KB total)
    float* part = (float*)smem;
    {
        float* pw = part + wid * 2048;
        #pragma unroll
        for (int vf = 0; vf < 4; vf++) {
            #pragma unroll
            for (int nf = 0; nf < 4; nf++) {
                int v = vf * 16 + g, sl = nf * 8 + t2 * 2;
                pw[(v + 0) * 32 + sl]     = o[vf][nf][0];
                pw[(v + 0) * 32 + sl + 1] = o[vf][nf][1];
                pw[(v + 8) * 32 + sl]     = o[vf][nf][2];
                pw[(v + 8) * 32 + sl + 1] = o[vf][nf][3];
            }
        }
    }
    __syncthreads();
    if (tid < 64) l_sm[tid] = red[tid] + red[64 + tid];
    __syncthreads();

    // final: sum 2 t-half partials, normalize, pack, store
    uint32_t* Ohp = g_Oh + (size_t)bh * DK * (TDIM / 2);
    uint32_t* Olp = g_Ol + (size_t)bh * DK * (TDIM / 2);
    int v = tid >> 1;
    #pragma unroll
    for (int j = 0; j < 16; j++) {
        int sp = (tid & 1) * 16 + j;          // s pair index 0..31
        int s  = sp * 2;
        int sg = s >> 5;                       // s-group (0/1)
        const float* r0 = part + (sg * 2 + 0) * 2048 + v * 32;
        const float* r1 = part + (sg * 2 + 1) * 2048 + v * 32;
        int sl = s & 31;
        float f0 = (r0[sl]     + r1[sl])     / l_sm[s];
        float f1 = (r0[sl + 1] + r1[sl + 1]) / l_sm[s + 1];
        uint32_t hp, lp; split2(f0, f1, hp, lp);
        size_t ix = (size_t)v * (TDIM / 2) + s0 / 2 + sp;
        Ohp[ix] = hp; Olp[ix] = lp;
    }
}

// ---------------------------------------------------------------------------
extern "C" void kernel_launch(void* const* d_in, const int* in_sizes, int n_in,
                              void* d_out, int out_size)
{
    const float* x    = (const float*)d_in[0];
    const float* y    = (const float*)d_in[1];
    const float* mask = (const float*)d_in[2];
    const float* Wk   = (const float*)d_in[3];
    const float* Wv   = (const float*)d_in[4];
    const float* Wq   = (const float*)d_in[5];
    const float* W    = (const float*)d_in[6];
    const float* bias = (const float*)d_in[7];
    float* out = (float*)d_out;

    cudaFuncSetAttribute(gemm_mma, cudaFuncAttributeMaxDynamicSharedMemorySize,
                         GEMM_SMEM);
    cudaFuncSetAttribute(attn_mma, cudaFuncAttributeMaxDynamicSharedMemorySize,
                         ATTN_SMEM);

    // 0) split all fp32 inputs into packed bf16 hi/lo
    prep_split<<<PREP_THREADS / 256, 256>>>(x, y, Wk, Wv, Wq, W);
    // 1) K,V,Q projections — R12 config (z = proj*2 + batch)
    gemm_mma<<<dim3(16, 4, 6), 256, GEMM_SMEM>>>(bias, out, 0);
    // 2) HMMA flash attention — 64-t tiles, 55 KB smem, 3 CTAs/SM target
    attn_mma<<<dim3(32, NBH), 128, ATTN_SMEM>>>(mask);
    // 3) output projection + bias
    gemm_mma<<<dim3(16, 4, 2), 256, GEMM_SMEM>>>(bias, out, 6);
}